// round 2
// baseline (speedup 1.0000x reference)
#include <cuda_runtime.h>

#define H      64
#define INF    128
#define NREL   8
#define NMAX   100000
#define EMAX   1600000

// ---- scratch (static device arrays; no allocation allowed) ----
__device__ __align__(128) float g_h  [NMAX * H];   // node features
__device__ __align__(128) float g_hm [NMAX * H];   // h @ W_msg
__device__ __align__(128) float g_out[NMAX * H];   // aggregated messages
__device__ __align__(128) float g_ps [NMAX];       // hm . a_src
__device__ __align__(128) float g_pd [NMAX];       // hm . a_dst
__device__ __align__(128) float g_s  [NMAX];       // softmax denominators
__device__ __align__(128) float g_ex [EMAX];       // exp(e) per edge
__device__ __align__(128) float g_q  [NREL];       // per-relation logit term

// ---------------------------------------------------------------
// K0: h = relu(x @ W_in + b_in). 32-node tile, W in smem.
// ---------------------------------------------------------------
__global__ __launch_bounds__(256) void k_input(
    const float* __restrict__ x, const float* __restrict__ W,
    const float* __restrict__ b, int N)
{
    __shared__ float Ws[INF * H];     // 32KB
    __shared__ float xs[32 * INF];    // 16KB
    int t = threadIdx.x;
    for (int j = t; j < INF * H / 4; j += 256)
        ((float4*)Ws)[j] = ((const float4*)W)[j];
    int n0 = blockIdx.x * 32;
    for (int j = t; j < 32 * INF / 4; j += 256) {
        int node = n0 + (j >> 5);     // 32 float4 per row
        float4 v = make_float4(0.f, 0.f, 0.f, 0.f);
        if (node < N) v = ((const float4*)x)[n0 * (INF / 4) + j];
        ((float4*)xs)[j] = v;
    }
    __syncthreads();
    int colq = (t & 15) * 4;
    int row  = t >> 4;                // 0..15, each handles 2 nodes
    float acc[2][4];
    #pragma unroll
    for (int j = 0; j < 2; j++)
        for (int c = 0; c < 4; c++) acc[j][c] = 0.f;
    #pragma unroll 4
    for (int k = 0; k < INF; k++) {
        float4 w4 = *(float4*)&Ws[k * H + colq];
        float h0 = xs[(row * 2 + 0) * INF + k];
        float h1 = xs[(row * 2 + 1) * INF + k];
        acc[0][0] += h0 * w4.x; acc[0][1] += h0 * w4.y;
        acc[0][2] += h0 * w4.z; acc[0][3] += h0 * w4.w;
        acc[1][0] += h1 * w4.x; acc[1][1] += h1 * w4.y;
        acc[1][2] += h1 * w4.z; acc[1][3] += h1 * w4.w;
    }
    float4 bb = *(const float4*)&b[colq];
    #pragma unroll
    for (int j = 0; j < 2; j++) {
        int node = n0 + row * 2 + j;
        if (node < N) {
            float4 o;
            o.x = fmaxf(acc[j][0] + bb.x, 0.f);
            o.y = fmaxf(acc[j][1] + bb.y, 0.f);
            o.z = fmaxf(acc[j][2] + bb.z, 0.f);
            o.w = fmaxf(acc[j][3] + bb.w, 0.f);
            *(float4*)&g_h[node * H + colq] = o;
        }
    }
}

// ---------------------------------------------------------------
// K1: hm = h @ W_msg;  p_dst = hm.a_dst, p_src = hm.a_src (fused)
// 64-node tile.
// ---------------------------------------------------------------
__global__ __launch_bounds__(256) void k_msg(
    const float* __restrict__ Wm, const float* __restrict__ att, int N)
{
    __shared__ float Ws[H * H];    // 16KB
    __shared__ float hs[64 * H];   // 16KB
    __shared__ float os[64 * H];   // 16KB
    int t = threadIdx.x;
    for (int j = t; j < H * H / 4; j += 256)
        ((float4*)Ws)[j] = ((const float4*)Wm)[j];
    int n0 = blockIdx.x * 64;
    for (int j = t; j < 64 * H / 4; j += 256) {
        int node = n0 + (j >> 4);  // 16 float4 per row
        float4 v = make_float4(0.f, 0.f, 0.f, 0.f);
        if (node < N) v = ((const float4*)g_h)[n0 * (H / 4) + j];
        ((float4*)hs)[j] = v;
    }
    __syncthreads();
    int colq = (t & 15) * 4;
    int row  = t >> 4;             // each row handles nodes row, row+16, row+32, row+48
    float acc[4][4];
    #pragma unroll
    for (int j = 0; j < 4; j++)
        for (int c = 0; c < 4; c++) acc[j][c] = 0.f;
    #pragma unroll 4
    for (int k = 0; k < H; k++) {
        float4 w4 = *(float4*)&Ws[k * H + colq];
        #pragma unroll
        for (int j = 0; j < 4; j++) {
            float hv = hs[(row + 16 * j) * H + k];
            acc[j][0] += hv * w4.x; acc[j][1] += hv * w4.y;
            acc[j][2] += hv * w4.z; acc[j][3] += hv * w4.w;
        }
    }
    #pragma unroll
    for (int j = 0; j < 4; j++) {
        int nl = row + 16 * j;
        int node = n0 + nl;
        float4 o = make_float4(acc[j][0], acc[j][1], acc[j][2], acc[j][3]);
        *(float4*)&os[nl * H + colq] = o;
        if (node < N) *(float4*)&g_hm[node * H + colq] = o;
    }
    __syncthreads();
    // attention scalar reduce: warp w handles nodes w*8 .. w*8+7
    int warp = t >> 5, lane = t & 31;
    float ad0 = att[lane],     ad1 = att[lane + 32];       // a_dst
    float as0 = att[H + lane], as1 = att[H + lane + 32];   // a_src
    for (int jj = 0; jj < 8; jj++) {
        int nl = warp * 8 + jj;
        float v0 = os[nl * H + lane], v1 = os[nl * H + lane + 32];
        float pd = v0 * ad0 + v1 * ad1;
        float ps = v0 * as0 + v1 * as1;
        #pragma unroll
        for (int o = 16; o; o >>= 1) {
            pd += __shfl_xor_sync(0xffffffffu, pd, o);
            ps += __shfl_xor_sync(0xffffffffu, ps, o);
        }
        int node = n0 + nl;
        if (lane == 0 && node < N) { g_pd[node] = pd; g_ps[node] = ps; }
    }
}

// ---------------------------------------------------------------
// Kq: q[t] = (rel_emb[t] @ W_relproj) . a_rel   (8 warps)
// ---------------------------------------------------------------
__global__ __launch_bounds__(256) void k_q(
    const float* __restrict__ rel, const float* __restrict__ Wp,
    const float* __restrict__ att)
{
    int warp = threadIdx.x >> 5, lane = threadIdx.x & 31;
    if (warp < NREL) {
        float acc = 0.f;
        for (int hh = lane; hh < H; hh += 32) {
            float v = 0.f;
            #pragma unroll
            for (int r = 0; r < 16; r++) v += rel[warp * 16 + r] * Wp[r * H + hh];
            acc += v * att[2 * H + hh];
        }
        #pragma unroll
        for (int o = 16; o; o >>= 1) acc += __shfl_xor_sync(0xffffffffu, acc, o);
        if (lane == 0) g_q[warp] = acc;
    }
}

// ---------------------------------------------------------------
// Kinit: zero accumulators
// ---------------------------------------------------------------
__global__ __launch_bounds__(256) void k_init(int N)
{
    int i = blockIdx.x * blockDim.x + threadIdx.x;
    if (i < N * (H / 4)) ((float4*)g_out)[i] = make_float4(0.f, 0.f, 0.f, 0.f);
    if (i < N) g_s[i] = 0.f;
}

// ---------------------------------------------------------------
// K2: edge logits -> exp -> denominator accumulate
// (max-subtraction removed: alpha is invariant to it; e is O(1) here)
// ---------------------------------------------------------------
__global__ __launch_bounds__(256) void k_edge(
    const int* __restrict__ src, const int* __restrict__ dst,
    const int* __restrict__ typ, const float* __restrict__ conf, int E)
{
    int i = blockIdx.x * blockDim.x + threadIdx.x;
    if (i >= E) return;
    int d  = dst[i];
    int sn = src[i];
    int tt = min(max(typ[i], 0), NREL - 1);
    float e = g_pd[d] + g_ps[sn] + g_q[tt];
    e = e > 0.f ? e : 0.2f * e;                       // leaky_relu(0.2)
    e += 0.1f * __logf(fmaxf(conf[i], 1e-6f));
    float ex = __expf(e);
    g_ex[i] = ex;
    atomicAdd(&g_s[d], ex);
}

// ---------------------------------------------------------------
// K3: weighted scatter. 16 lanes per edge, float4 gather + float4 RED.
// ---------------------------------------------------------------
__global__ __launch_bounds__(256) void k_scatter(
    const int* __restrict__ src, const int* __restrict__ dst, int E)
{
    int gt = blockIdx.x * blockDim.x + threadIdx.x;
    int i  = gt >> 4;                 // edge index
    if (i >= E) return;
    int l  = gt & 15;                 // 0..15 -> float4 chunk
    int d  = dst[i];
    int sn = src[i];
    float alpha = g_ex[i] / g_s[d];
    float4 v = *(const float4*)&g_hm[sn * H + l * 4];
    float4 w = make_float4(v.x * alpha, v.y * alpha, v.z * alpha, v.w * alpha);
    atomicAdd((float4*)&g_out[d * H + l * 4], w);
}

// ---------------------------------------------------------------
// K4: h = layernorm(h + relu(out + bias)); warp per node.
// hout == nullptr -> write back to g_h, else to hout (final output).
// ---------------------------------------------------------------
__global__ __launch_bounds__(256) void k_update(
    const float* __restrict__ bias, const float* __restrict__ lng,
    const float* __restrict__ lnb, float* __restrict__ hout, int N)
{
    int lane = threadIdx.x & 31;
    int n = (blockIdx.x * blockDim.x + threadIdx.x) >> 5;
    if (n >= N) return;
    float* outp = hout ? hout : g_h;
    float h0 = g_h[n * H + lane], h1 = g_h[n * H + lane + 32];
    float o0 = fmaxf(g_out[n * H + lane]      + bias[lane],      0.f);
    float o1 = fmaxf(g_out[n * H + lane + 32] + bias[lane + 32], 0.f);
    float v0 = h0 + o0, v1 = h1 + o1;
    float s = v0 + v1;
    #pragma unroll
    for (int o = 16; o; o >>= 1) s += __shfl_xor_sync(0xffffffffu, s, o);
    float mu = s * (1.f / H);
    float d0 = v0 - mu, d1 = v1 - mu;
    float vs = d0 * d0 + d1 * d1;
    #pragma unroll
    for (int o = 16; o; o >>= 1) vs += __shfl_xor_sync(0xffffffffu, vs, o);
    float inv = rsqrtf(vs * (1.f / H) + 1e-5f);
    outp[n * H + lane]      = d0 * inv * lng[lane]      + lnb[lane];
    outp[n * H + lane + 32] = d1 * inv * lng[lane + 32] + lnb[lane + 32];
}

// ---------------------------------------------------------------
extern "C" void kernel_launch(void* const* d_in, const int* in_sizes, int n_in,
                              void* d_out, int out_size)
{
    const float* x         = (const float*)d_in[0];
    const float* W_in      = (const float*)d_in[1];
    const float* b_in      = (const float*)d_in[2];
    const float* W_msg     = (const float*)d_in[3];
    const float* rel_emb   = (const float*)d_in[4];
    const float* W_relproj = (const float*)d_in[5];
    const float* att_vec   = (const float*)d_in[6];
    const float* bias      = (const float*)d_in[7];
    const float* ln_g      = (const float*)d_in[8];
    const float* ln_b      = (const float*)d_in[9];
    const float* edge_attr = (const float*)d_in[10];
    const int*   edge_index= (const int*)d_in[11];
    const int*   edge_type = (const int*)d_in[12];
    float* out = (float*)d_out;

    int N = in_sizes[0] / INF;        // 100000
    int E = in_sizes[12];             // 1600000
    int L = in_sizes[7] / H;          // 2
    const int* src = edge_index;
    const int* dst = edge_index + E;

    k_input<<<(N + 31) / 32, 256>>>(x, W_in, b_in, N);

    for (int l = 0; l < L; l++) {
        k_q<<<1, 256>>>(rel_emb + l * NREL * 16,
                        W_relproj + l * 16 * H,
                        att_vec + l * 3 * H);
        k_init<<<(N * (H / 4) + 255) / 256, 256>>>(N);
        k_msg<<<(N + 63) / 64, 256>>>(W_msg + l * H * H,
                                      att_vec + l * 3 * H, N);
        k_edge<<<(E + 255) / 256, 256>>>(src, dst, edge_type, edge_attr, E);
        k_scatter<<<(E * 16 + 255) / 256, 256>>>(src, dst, E);
        k_update<<<(N * 32 + 255) / 256, 256>>>(bias + l * H,
                                                ln_g + l * H, ln_b + l * H,
                                                (l == L - 1) ? out : (float*)nullptr,
                                                N);
    }
}

// round 3
// speedup vs baseline: 1.3003x; 1.3003x over previous
#include <cuda_runtime.h>

#define H      64
#define INF    128
#define NREL   8
#define NMAX   100000
#define EMAX   1600000

// ---- scratch (static device arrays; no allocation allowed) ----
__device__ __align__(128) float g_h  [NMAX * H];     // node features
__device__ __align__(128) float g_hm [NMAX * H];     // h @ W_msg
__device__ __align__(128) float g_out[NMAX * H];     // aggregated (normalized) messages
__device__ __align__(128) float g_ps [NMAX];         // hm . a_src
__device__ __align__(128) float g_pd [NMAX];         // hm . a_dst
__device__ __align__(128) float g_q  [NREL];         // per-relation logit term
// dst-sorted edge structure (built once per launch, reused across layers)
__device__ __align__(128) unsigned g_srcs[EMAX];     // src | (typ<<20)
__device__ __align__(128) float    g_cf  [EMAX];     // 0.1*log(max(conf,1e-6))
__device__ __align__(128) int g_deg [NMAX];
__device__ __align__(128) int g_cur [NMAX];
__device__ __align__(128) int g_off [NMAX + 1];
__device__ __align__(128) int g_bsum[128];
__device__ __align__(128) int g_boff[128];

// ---------------------------------------------------------------
// K0: h = relu(x @ W_in + b_in). 32-node tile, W in smem.
// ---------------------------------------------------------------
__global__ __launch_bounds__(256) void k_input(
    const float* __restrict__ x, const float* __restrict__ W,
    const float* __restrict__ b, int N)
{
    __shared__ float Ws[INF * H];     // 32KB
    __shared__ float xs[32 * INF];    // 16KB
    int t = threadIdx.x;
    for (int j = t; j < INF * H / 4; j += 256)
        ((float4*)Ws)[j] = ((const float4*)W)[j];
    int n0 = blockIdx.x * 32;
    for (int j = t; j < 32 * INF / 4; j += 256) {
        int node = n0 + (j >> 5);
        float4 v = make_float4(0.f, 0.f, 0.f, 0.f);
        if (node < N) v = ((const float4*)x)[n0 * (INF / 4) + j];
        ((float4*)xs)[j] = v;
    }
    __syncthreads();
    int colq = (t & 15) * 4;
    int row  = t >> 4;
    float acc[2][4];
    #pragma unroll
    for (int j = 0; j < 2; j++)
        for (int c = 0; c < 4; c++) acc[j][c] = 0.f;
    #pragma unroll 4
    for (int k = 0; k < INF; k++) {
        float4 w4 = *(float4*)&Ws[k * H + colq];
        float h0 = xs[(row * 2 + 0) * INF + k];
        float h1 = xs[(row * 2 + 1) * INF + k];
        acc[0][0] += h0 * w4.x; acc[0][1] += h0 * w4.y;
        acc[0][2] += h0 * w4.z; acc[0][3] += h0 * w4.w;
        acc[1][0] += h1 * w4.x; acc[1][1] += h1 * w4.y;
        acc[1][2] += h1 * w4.z; acc[1][3] += h1 * w4.w;
    }
    float4 bb = *(const float4*)&b[colq];
    #pragma unroll
    for (int j = 0; j < 2; j++) {
        int node = n0 + row * 2 + j;
        if (node < N) {
            float4 o;
            o.x = fmaxf(acc[j][0] + bb.x, 0.f);
            o.y = fmaxf(acc[j][1] + bb.y, 0.f);
            o.z = fmaxf(acc[j][2] + bb.z, 0.f);
            o.w = fmaxf(acc[j][3] + bb.w, 0.f);
            *(float4*)&g_h[node * H + colq] = o;
        }
    }
}

// ---------------------------------------------------------------
// K1: hm = h @ W_msg;  p_dst = hm.a_dst, p_src = hm.a_src (fused)
// ---------------------------------------------------------------
__global__ __launch_bounds__(256) void k_msg(
    const float* __restrict__ Wm, const float* __restrict__ att, int N)
{
    __shared__ float Ws[H * H];
    __shared__ float hs[64 * H];
    __shared__ float os[64 * H];
    int t = threadIdx.x;
    for (int j = t; j < H * H / 4; j += 256)
        ((float4*)Ws)[j] = ((const float4*)Wm)[j];
    int n0 = blockIdx.x * 64;
    for (int j = t; j < 64 * H / 4; j += 256) {
        int node = n0 + (j >> 4);
        float4 v = make_float4(0.f, 0.f, 0.f, 0.f);
        if (node < N) v = ((const float4*)g_h)[n0 * (H / 4) + j];
        ((float4*)hs)[j] = v;
    }
    __syncthreads();
    int colq = (t & 15) * 4;
    int row  = t >> 4;
    float acc[4][4];
    #pragma unroll
    for (int j = 0; j < 4; j++)
        for (int c = 0; c < 4; c++) acc[j][c] = 0.f;
    #pragma unroll 4
    for (int k = 0; k < H; k++) {
        float4 w4 = *(float4*)&Ws[k * H + colq];
        #pragma unroll
        for (int j = 0; j < 4; j++) {
            float hv = hs[(row + 16 * j) * H + k];
            acc[j][0] += hv * w4.x; acc[j][1] += hv * w4.y;
            acc[j][2] += hv * w4.z; acc[j][3] += hv * w4.w;
        }
    }
    #pragma unroll
    for (int j = 0; j < 4; j++) {
        int nl = row + 16 * j;
        int node = n0 + nl;
        float4 o = make_float4(acc[j][0], acc[j][1], acc[j][2], acc[j][3]);
        *(float4*)&os[nl * H + colq] = o;
        if (node < N) *(float4*)&g_hm[node * H + colq] = o;
    }
    __syncthreads();
    int warp = t >> 5, lane = t & 31;
    float ad0 = att[lane],     ad1 = att[lane + 32];
    float as0 = att[H + lane], as1 = att[H + lane + 32];
    for (int jj = 0; jj < 8; jj++) {
        int nl = warp * 8 + jj;
        float v0 = os[nl * H + lane], v1 = os[nl * H + lane + 32];
        float pd = v0 * ad0 + v1 * ad1;
        float ps = v0 * as0 + v1 * as1;
        #pragma unroll
        for (int o = 16; o; o >>= 1) {
            pd += __shfl_xor_sync(0xffffffffu, pd, o);
            ps += __shfl_xor_sync(0xffffffffu, ps, o);
        }
        int node = n0 + nl;
        if (lane == 0 && node < N) { g_pd[node] = pd; g_ps[node] = ps; }
    }
}

// ---------------------------------------------------------------
// Kq: q[t] = (rel_emb[t] @ W_relproj) . a_rel
// ---------------------------------------------------------------
__global__ __launch_bounds__(256) void k_q(
    const float* __restrict__ rel, const float* __restrict__ Wp,
    const float* __restrict__ att)
{
    int warp = threadIdx.x >> 5, lane = threadIdx.x & 31;
    if (warp < NREL) {
        float acc = 0.f;
        for (int hh = lane; hh < H; hh += 32) {
            float v = 0.f;
            #pragma unroll
            for (int r = 0; r < 16; r++) v += rel[warp * 16 + r] * Wp[r * H + hh];
            acc += v * att[2 * H + hh];
        }
        #pragma unroll
        for (int o = 16; o; o >>= 1) acc += __shfl_xor_sync(0xffffffffu, acc, o);
        if (lane == 0) g_q[warp] = acc;
    }
}

// ---------------------------------------------------------------
// Preprocessing: counting sort of edges by dst (once per launch).
// ---------------------------------------------------------------
__global__ __launch_bounds__(256) void k_zero(int N)
{
    int i = blockIdx.x * blockDim.x + threadIdx.x;
    if (i < N) { g_deg[i] = 0; g_cur[i] = 0; }
}

__global__ __launch_bounds__(256) void k_hist(const int* __restrict__ dst, int E)
{
    int i = blockIdx.x * blockDim.x + threadIdx.x;
    if (i < E) atomicAdd(&g_deg[dst[i]], 1);
}

// inclusive scan over 1024-element chunks
__global__ __launch_bounds__(1024) void k_scan1(int N)
{
    __shared__ int s[1024];
    int t = threadIdx.x;
    int i = blockIdx.x * 1024 + t;
    s[t] = (i < N) ? g_deg[i] : 0;
    __syncthreads();
    #pragma unroll
    for (int o = 1; o < 1024; o <<= 1) {
        int v = (t >= o) ? s[t - o] : 0;
        __syncthreads();
        s[t] += v;
        __syncthreads();
    }
    if (i < N) g_off[i + 1] = s[t];
    if (t == 1023) g_bsum[blockIdx.x] = s[1023];
}

__global__ __launch_bounds__(128) void k_scan2(int nb)
{
    __shared__ int s[128];
    int t = threadIdx.x;
    s[t] = (t < nb) ? g_bsum[t] : 0;
    __syncthreads();
    #pragma unroll
    for (int o = 1; o < 128; o <<= 1) {
        int v = (t >= o) ? s[t - o] : 0;
        __syncthreads();
        s[t] += v;
        __syncthreads();
    }
    if (t < nb) g_boff[t] = t ? s[t - 1] : 0;
}

__global__ __launch_bounds__(1024) void k_scan3(int N)
{
    int i = blockIdx.x * 1024 + threadIdx.x;
    if (i < N) g_off[i + 1] += g_boff[blockIdx.x];
    if (i == 0) g_off[0] = 0;
}

__global__ __launch_bounds__(256) void k_sortscatter(
    const int* __restrict__ src, const int* __restrict__ dst,
    const int* __restrict__ typ, const float* __restrict__ conf, int E)
{
    int i = blockIdx.x * blockDim.x + threadIdx.x;
    if (i >= E) return;
    int d = dst[i];
    int pos = g_off[d] + atomicAdd(&g_cur[d], 1);
    int t = min(max(typ[i], 0), NREL - 1);
    g_srcs[pos] = (unsigned)src[i] | ((unsigned)t << 20);
    g_cf[pos]   = 0.1f * __logf(fmaxf(conf[i], 1e-6f));
}

// ---------------------------------------------------------------
// K_aggr: warp-per-node fused softmax + weighted gather-sum.
// lanes 0-15 handle even edges of segment, 16-31 odd edges.
// No atomics: one coalesced 256B store per node.
// ---------------------------------------------------------------
__global__ __launch_bounds__(256) void k_aggr(int N)
{
    int warp = (blockIdx.x * blockDim.x + threadIdx.x) >> 5;
    if (warp >= N) return;
    int lane = threadIdx.x & 31;
    int half = lane >> 4;
    int l    = lane & 15;
    int beg = g_off[warp], end = g_off[warp + 1];
    float pdn = g_pd[warp];
    float4 acc = make_float4(0.f, 0.f, 0.f, 0.f);
    float ssum = 0.f;
    for (int j = beg + half; j < end; j += 2) {
        unsigned p = g_srcs[j];
        int s = p & 0xFFFFF;
        int tt = p >> 20;
        float e = pdn + g_ps[s] + g_q[tt];
        e = e > 0.f ? e : 0.2f * e;                 // leaky_relu(0.2)
        e += g_cf[j];
        float ex = __expf(e);
        float4 v = *(const float4*)&g_hm[s * H + l * 4];
        acc.x += ex * v.x; acc.y += ex * v.y;
        acc.z += ex * v.z; acc.w += ex * v.w;
        ssum += ex;                                  // identical across the 16 lanes of this half
    }
    // combine the two halves (lane l <- lane l + lane l+16)
    acc.x += __shfl_xor_sync(0xffffffffu, acc.x, 16);
    acc.y += __shfl_xor_sync(0xffffffffu, acc.y, 16);
    acc.z += __shfl_xor_sync(0xffffffffu, acc.z, 16);
    acc.w += __shfl_xor_sync(0xffffffffu, acc.w, 16);
    ssum  += __shfl_xor_sync(0xffffffffu, ssum,  16);
    float inv = (ssum > 0.f) ? (1.f / ssum) : 0.f;   // deg==0 -> out 0
    if (half == 0) {
        float4 o = make_float4(acc.x * inv, acc.y * inv, acc.z * inv, acc.w * inv);
        *(float4*)&g_out[warp * H + l * 4] = o;
    }
}

// ---------------------------------------------------------------
// K4: h = layernorm(h + relu(out + bias)); warp per node.
// ---------------------------------------------------------------
__global__ __launch_bounds__(256) void k_update(
    const float* __restrict__ bias, const float* __restrict__ lng,
    const float* __restrict__ lnb, float* __restrict__ hout, int N)
{
    int lane = threadIdx.x & 31;
    int n = (blockIdx.x * blockDim.x + threadIdx.x) >> 5;
    if (n >= N) return;
    float* outp = hout ? hout : g_h;
    float h0 = g_h[n * H + lane], h1 = g_h[n * H + lane + 32];
    float o0 = fmaxf(g_out[n * H + lane]      + bias[lane],      0.f);
    float o1 = fmaxf(g_out[n * H + lane + 32] + bias[lane + 32], 0.f);
    float v0 = h0 + o0, v1 = h1 + o1;
    float s = v0 + v1;
    #pragma unroll
    for (int o = 16; o; o >>= 1) s += __shfl_xor_sync(0xffffffffu, s, o);
    float mu = s * (1.f / H);
    float d0 = v0 - mu, d1 = v1 - mu;
    float vs = d0 * d0 + d1 * d1;
    #pragma unroll
    for (int o = 16; o; o >>= 1) vs += __shfl_xor_sync(0xffffffffu, vs, o);
    float inv = rsqrtf(vs * (1.f / H) + 1e-5f);
    outp[n * H + lane]      = d0 * inv * lng[lane]      + lnb[lane];
    outp[n * H + lane + 32] = d1 * inv * lng[lane + 32] + lnb[lane + 32];
}

// ---------------------------------------------------------------
extern "C" void kernel_launch(void* const* d_in, const int* in_sizes, int n_in,
                              void* d_out, int out_size)
{
    const float* x         = (const float*)d_in[0];
    const float* W_in      = (const float*)d_in[1];
    const float* b_in      = (const float*)d_in[2];
    const float* W_msg     = (const float*)d_in[3];
    const float* rel_emb   = (const float*)d_in[4];
    const float* W_relproj = (const float*)d_in[5];
    const float* att_vec   = (const float*)d_in[6];
    const float* bias      = (const float*)d_in[7];
    const float* ln_g      = (const float*)d_in[8];
    const float* ln_b      = (const float*)d_in[9];
    const float* edge_attr = (const float*)d_in[10];
    const int*   edge_index= (const int*)d_in[11];
    const int*   edge_type = (const int*)d_in[12];
    float* out = (float*)d_out;

    int N = in_sizes[0] / INF;        // 100000
    int E = in_sizes[12];             // 1600000
    int L = in_sizes[7] / H;          // 2
    const int* src = edge_index;
    const int* dst = edge_index + E;
    int nb = (N + 1023) / 1024;

    k_input<<<(N + 31) / 32, 256>>>(x, W_in, b_in, N);

    // one-time dst-sorted edge structure (layer-invariant)
    k_zero<<<(N + 255) / 256, 256>>>(N);
    k_hist<<<(E + 255) / 256, 256>>>(dst, E);
    k_scan1<<<nb, 1024>>>(N);
    k_scan2<<<1, 128>>>(nb);
    k_scan3<<<nb, 1024>>>(N);
    k_sortscatter<<<(E + 255) / 256, 256>>>(src, dst, edge_type, edge_attr, E);

    for (int l = 0; l < L; l++) {
        k_q<<<1, 256>>>(rel_emb + l * NREL * 16,
                        W_relproj + l * 16 * H,
                        att_vec + l * 3 * H);
        k_msg<<<(N + 63) / 64, 256>>>(W_msg + l * H * H,
                                      att_vec + l * 3 * H, N);
        k_aggr<<<(N * 32 + 255) / 256, 256>>>(N);
        k_update<<<(N * 32 + 255) / 256, 256>>>(bias + l * H,
                                                ln_g + l * H, ln_b + l * H,
                                                (l == L - 1) ? out : (float*)nullptr,
                                                N);
    }
}

// round 4
// speedup vs baseline: 1.4074x; 1.0823x over previous
#include <cuda_runtime.h>

#define H      64
#define INF    128
#define NREL   8
#define NMAX   100000
#define EMAX   1600000

__device__ __forceinline__ void fma4(float4& a, float s, const float4& w) {
    a.x += s * w.x; a.y += s * w.y; a.z += s * w.z; a.w += s * w.w;
}

// ---- scratch ----
__device__ __align__(128) float g_h  [NMAX * H];
__device__ __align__(128) float g_hm [NMAX * H];
__device__ __align__(128) float g_ps [NMAX];
__device__ __align__(128) float g_pd [NMAX];
__device__ __align__(128) float g_q  [NREL];
__device__ __align__(128) unsigned g_srcs[EMAX];   // src | (typ<<20), dst-sorted
__device__ __align__(128) int      g_dsts[EMAX];   // dst per sorted edge
__device__ __align__(128) float    g_cf  [EMAX];   // 0.1*log(max(conf,1e-6))
__device__ __align__(128) float    g_ex  [EMAX];   // exp(e) per sorted edge
__device__ __align__(128) int g_deg [NMAX];
__device__ __align__(128) int g_cur [NMAX];
__device__ __align__(128) int g_off [NMAX + 1];
__device__ __align__(128) int g_bsum[128];
__device__ __align__(128) int g_boff[128];

// ---------------------------------------------------------------
// K0: h = relu(x @ W_in + b_in). 32-node tile; 2 nodes x 4 cols/thread.
// ---------------------------------------------------------------
__global__ __launch_bounds__(256) void k_input(
    const float* __restrict__ x, const float* __restrict__ W,
    const float* __restrict__ b, int N)
{
    __shared__ float Ws[INF * H];     // 32KB
    __shared__ float xs[32 * INF];    // 16KB
    int t = threadIdx.x;
    for (int j = t; j < INF * H / 4; j += 256)
        ((float4*)Ws)[j] = ((const float4*)W)[j];
    int n0 = blockIdx.x * 32;
    for (int j = t; j < 32 * INF / 4; j += 256) {
        int node = n0 + (j >> 5);
        float4 v = make_float4(0.f, 0.f, 0.f, 0.f);
        if (node < N) v = ((const float4*)x)[n0 * (INF / 4) + j];
        ((float4*)xs)[j] = v;
    }
    __syncthreads();
    int cg = t & 15;                  // col group, cols cg*4..cg*4+3
    int rg = t >> 4;                  // nodes rg*2, rg*2+1
    const float4* Wv = (const float4*)Ws;
    const float4* Xv = (const float4*)xs;
    float4 a0 = make_float4(0.f,0.f,0.f,0.f);
    float4 a1 = make_float4(0.f,0.f,0.f,0.f);
    #pragma unroll 8
    for (int k4 = 0; k4 < INF / 4; k4++) {
        float4 w0 = Wv[(k4*4+0)*16 + cg];
        float4 w1 = Wv[(k4*4+1)*16 + cg];
        float4 w2 = Wv[(k4*4+2)*16 + cg];
        float4 w3 = Wv[(k4*4+3)*16 + cg];
        float4 x0 = Xv[(rg*2+0)*32 + k4];
        float4 x1 = Xv[(rg*2+1)*32 + k4];
        fma4(a0, x0.x, w0); fma4(a0, x0.y, w1); fma4(a0, x0.z, w2); fma4(a0, x0.w, w3);
        fma4(a1, x1.x, w0); fma4(a1, x1.y, w1); fma4(a1, x1.z, w2); fma4(a1, x1.w, w3);
    }
    float4 bb = *(const float4*)&b[cg * 4];
    int node0 = n0 + rg * 2;
    if (node0 < N) {
        float4 o = make_float4(fmaxf(a0.x+bb.x,0.f), fmaxf(a0.y+bb.y,0.f),
                               fmaxf(a0.z+bb.z,0.f), fmaxf(a0.w+bb.w,0.f));
        *(float4*)&g_h[node0 * H + cg * 4] = o;
    }
    if (node0 + 1 < N) {
        float4 o = make_float4(fmaxf(a1.x+bb.x,0.f), fmaxf(a1.y+bb.y,0.f),
                               fmaxf(a1.z+bb.z,0.f), fmaxf(a1.w+bb.w,0.f));
        *(float4*)&g_h[(node0+1) * H + cg * 4] = o;
    }
}

// ---------------------------------------------------------------
// K1: hm = h @ W_msg; fused pd/ps. 64-node tile; 4 nodes x 4 cols/thread.
// ---------------------------------------------------------------
__global__ __launch_bounds__(256) void k_msg(
    const float* __restrict__ Wm, const float* __restrict__ att, int N)
{
    __shared__ float Ws[H * H];    // 16KB
    __shared__ float hs[64 * H];   // 16KB
    int t = threadIdx.x;
    for (int j = t; j < H * H / 4; j += 256)
        ((float4*)Ws)[j] = ((const float4*)Wm)[j];
    int n0 = blockIdx.x * 64;
    for (int j = t; j < 64 * H / 4; j += 256) {
        int node = n0 + (j >> 4);
        float4 v = make_float4(0.f, 0.f, 0.f, 0.f);
        if (node < N) v = ((const float4*)g_h)[n0 * (H / 4) + j];
        ((float4*)hs)[j] = v;
    }
    __syncthreads();
    int cg = t & 15;
    int rg = t >> 4;                 // nodes rg*4 .. rg*4+3
    const float4* Wv = (const float4*)Ws;
    const float4* Hv = (const float4*)hs;
    float4 acc[4];
    #pragma unroll
    for (int n = 0; n < 4; n++) acc[n] = make_float4(0.f,0.f,0.f,0.f);
    #pragma unroll 4
    for (int k4 = 0; k4 < H / 4; k4++) {
        float4 w0 = Wv[(k4*4+0)*16 + cg];
        float4 w1 = Wv[(k4*4+1)*16 + cg];
        float4 w2 = Wv[(k4*4+2)*16 + cg];
        float4 w3 = Wv[(k4*4+3)*16 + cg];
        #pragma unroll
        for (int n = 0; n < 4; n++) {
            float4 hv = Hv[(rg*4+n)*16 + k4];
            fma4(acc[n], hv.x, w0); fma4(acc[n], hv.y, w1);
            fma4(acc[n], hv.z, w2); fma4(acc[n], hv.w, w3);
        }
    }
    // store hm
    #pragma unroll
    for (int n = 0; n < 4; n++) {
        int node = n0 + rg * 4 + n;
        if (node < N) *(float4*)&g_hm[node * H + cg * 4] = acc[n];
    }
    // attention scalars: partial dot over this thread's 4 cols, reduce over 16 col-threads
    float4 ad = *(const float4*)&att[cg * 4];
    float4 as = *(const float4*)&att[H + cg * 4];
    float pdv[4], psv[4];
    #pragma unroll
    for (int n = 0; n < 4; n++) {
        pdv[n] = acc[n].x*ad.x + acc[n].y*ad.y + acc[n].z*ad.z + acc[n].w*ad.w;
        psv[n] = acc[n].x*as.x + acc[n].y*as.y + acc[n].z*as.z + acc[n].w*as.w;
    }
    #pragma unroll
    for (int o = 8; o; o >>= 1) {
        #pragma unroll
        for (int n = 0; n < 4; n++) {
            pdv[n] += __shfl_xor_sync(0xffffffffu, pdv[n], o);
            psv[n] += __shfl_xor_sync(0xffffffffu, psv[n], o);
        }
    }
    if (cg == 0) {
        #pragma unroll
        for (int n = 0; n < 4; n++) {
            int node = n0 + rg * 4 + n;
            if (node < N) { g_pd[node] = pdv[n]; g_ps[node] = psv[n]; }
        }
    }
}

// ---------------------------------------------------------------
// Kq: q[t] = (rel_emb[t] @ W_relproj) . a_rel
// ---------------------------------------------------------------
__global__ __launch_bounds__(256) void k_q(
    const float* __restrict__ rel, const float* __restrict__ Wp,
    const float* __restrict__ att)
{
    int warp = threadIdx.x >> 5, lane = threadIdx.x & 31;
    if (warp < NREL) {
        float acc = 0.f;
        for (int hh = lane; hh < H; hh += 32) {
            float v = 0.f;
            #pragma unroll
            for (int r = 0; r < 16; r++) v += rel[warp * 16 + r] * Wp[r * H + hh];
            acc += v * att[2 * H + hh];
        }
        #pragma unroll
        for (int o = 16; o; o >>= 1) acc += __shfl_xor_sync(0xffffffffu, acc, o);
        if (lane == 0) g_q[warp] = acc;
    }
}

// ---------------------------------------------------------------
// Preprocessing: counting sort of edges by dst (once per launch).
// ---------------------------------------------------------------
__global__ __launch_bounds__(256) void k_zero(int N)
{
    int i = blockIdx.x * blockDim.x + threadIdx.x;
    if (i < N) { g_deg[i] = 0; g_cur[i] = 0; }
}

__global__ __launch_bounds__(256) void k_hist(const int* __restrict__ dst, int E)
{
    int i = blockIdx.x * blockDim.x + threadIdx.x;
    if (i < E) atomicAdd(&g_deg[dst[i]], 1);
}

// warp-shuffle inclusive scan over 1024-element chunks
__global__ __launch_bounds__(1024) void k_scan1(int N)
{
    __shared__ int ws[32];
    int t = threadIdx.x, lane = t & 31, w = t >> 5;
    int i = blockIdx.x * 1024 + t;
    int v = (i < N) ? g_deg[i] : 0;
    #pragma unroll
    for (int o = 1; o < 32; o <<= 1) {
        int u = __shfl_up_sync(0xffffffffu, v, o);
        if (lane >= o) v += u;
    }
    if (lane == 31) ws[w] = v;
    __syncthreads();
    if (w == 0) {
        int bsum = ws[lane];
        #pragma unroll
        for (int o = 1; o < 32; o <<= 1) {
            int u = __shfl_up_sync(0xffffffffu, bsum, o);
            if (lane >= o) bsum += u;
        }
        ws[lane] = bsum;
    }
    __syncthreads();
    if (w) v += ws[w - 1];
    if (i < N) g_off[i + 1] = v;
    if (t == 1023) g_bsum[blockIdx.x] = v;
}

__global__ __launch_bounds__(128) void k_scan2(int nb)
{
    __shared__ int s[128];
    int t = threadIdx.x;
    s[t] = (t < nb) ? g_bsum[t] : 0;
    __syncthreads();
    #pragma unroll
    for (int o = 1; o < 128; o <<= 1) {
        int v = (t >= o) ? s[t - o] : 0;
        __syncthreads();
        s[t] += v;
        __syncthreads();
    }
    if (t < nb) g_boff[t] = t ? s[t - 1] : 0;
}

__global__ __launch_bounds__(1024) void k_scan3(int N)
{
    int i = blockIdx.x * 1024 + threadIdx.x;
    if (i < N) g_off[i + 1] += g_boff[blockIdx.x];
    if (i == 0) g_off[0] = 0;
}

__global__ __launch_bounds__(256) void k_sortscatter(
    const int* __restrict__ src, const int* __restrict__ dst,
    const int* __restrict__ typ, const float* __restrict__ conf, int E)
{
    int i = blockIdx.x * blockDim.x + threadIdx.x;
    if (i >= E) return;
    int d = dst[i];
    int pos = g_off[d] + atomicAdd(&g_cur[d], 1);
    int t = min(max(typ[i], 0), NREL - 1);
    g_srcs[pos] = (unsigned)src[i] | ((unsigned)t << 20);
    g_dsts[pos] = d;
    g_cf[pos]   = 0.1f * __logf(fmaxf(conf[i], 1e-6f));
}

// ---------------------------------------------------------------
// K_w: edge-parallel coalesced logit + exp over sorted edges.
// ---------------------------------------------------------------
__global__ __launch_bounds__(256) void k_w(int E)
{
    int i = blockIdx.x * blockDim.x + threadIdx.x;
    if (i >= E) return;
    unsigned p = g_srcs[i];
    int d = g_dsts[i];
    float e = g_pd[d] + g_ps[p & 0xFFFFF] + g_q[p >> 20];
    e = e > 0.f ? e : 0.2f * e;
    e += g_cf[i];
    g_ex[i] = __expf(e);
}

// ---------------------------------------------------------------
// K_aggr: warp-per-node gather-sum over precomputed weights, fused
// with softmax normalization + residual + relu + layernorm.
// halves of warp take alternating edges; unroll x2 per half (MLP=4).
// ---------------------------------------------------------------
__global__ __launch_bounds__(256) void k_aggr(
    const float* __restrict__ bias, const float* __restrict__ lng,
    const float* __restrict__ lnb, float* __restrict__ hout, int N)
{
    int n = (blockIdx.x * blockDim.x + threadIdx.x) >> 5;
    if (n >= N) return;
    int lane = threadIdx.x & 31;
    int half = lane >> 4;
    int l    = lane & 15;
    int beg = g_off[n], end = g_off[n + 1];
    float4 acc = make_float4(0.f, 0.f, 0.f, 0.f);
    float ssum = 0.f;
    int j = beg + half;
    for (; j + 2 < end; j += 4) {
        unsigned p0 = g_srcs[j];
        unsigned p1 = g_srcs[j + 2];
        float e0 = g_ex[j];
        float e1 = g_ex[j + 2];
        float4 v0 = *(const float4*)&g_hm[(p0 & 0xFFFFF) * H + l * 4];
        float4 v1 = *(const float4*)&g_hm[(p1 & 0xFFFFF) * H + l * 4];
        fma4(acc, e0, v0);
        fma4(acc, e1, v1);
        ssum += e0 + e1;
    }
    for (; j < end; j += 2) {
        unsigned p = g_srcs[j];
        float e0 = g_ex[j];
        float4 v = *(const float4*)&g_hm[(p & 0xFFFFF) * H + l * 4];
        fma4(acc, e0, v);
        ssum += e0;
    }
    // combine halves: afterwards all 32 lanes hold identical (per-l) results
    acc.x += __shfl_xor_sync(0xffffffffu, acc.x, 16);
    acc.y += __shfl_xor_sync(0xffffffffu, acc.y, 16);
    acc.z += __shfl_xor_sync(0xffffffffu, acc.z, 16);
    acc.w += __shfl_xor_sync(0xffffffffu, acc.w, 16);
    ssum  += __shfl_xor_sync(0xffffffffu, ssum,  16);
    float inv = (ssum > 0.f) ? (1.f / ssum) : 0.f;
    // u = h + relu(msg + bias)
    float4 hv = *(const float4*)&g_h[n * H + l * 4];
    float4 bb = *(const float4*)&bias[l * 4];
    float4 u;
    u.x = hv.x + fmaxf(acc.x * inv + bb.x, 0.f);
    u.y = hv.y + fmaxf(acc.y * inv + bb.y, 0.f);
    u.z = hv.z + fmaxf(acc.z * inv + bb.z, 0.f);
    u.w = hv.w + fmaxf(acc.w * inv + bb.w, 0.f);
    // layernorm: 32 lanes hold 2x duplicated 64 values -> divide by 128
    float s = u.x + u.y + u.z + u.w;
    #pragma unroll
    for (int o = 16; o; o >>= 1) s += __shfl_xor_sync(0xffffffffu, s, o);
    float mu = s * (1.f / 128.f);
    float4 d4 = make_float4(u.x - mu, u.y - mu, u.z - mu, u.w - mu);
    float vs = d4.x*d4.x + d4.y*d4.y + d4.z*d4.z + d4.w*d4.w;
    #pragma unroll
    for (int o = 16; o; o >>= 1) vs += __shfl_xor_sync(0xffffffffu, vs, o);
    float invs = rsqrtf(vs * (1.f / 128.f) + 1e-5f);
    if (half == 0) {
        float4 g4 = *(const float4*)&lng[l * 4];
        float4 b2 = *(const float4*)&lnb[l * 4];
        float* outp = hout ? hout : g_h;
        float4 o4;
        o4.x = d4.x * invs * g4.x + b2.x;
        o4.y = d4.y * invs * g4.y + b2.y;
        o4.z = d4.z * invs * g4.z + b2.z;
        o4.w = d4.w * invs * g4.w + b2.w;
        *(float4*)&outp[n * H + l * 4] = o4;
    }
}

// ---------------------------------------------------------------
extern "C" void kernel_launch(void* const* d_in, const int* in_sizes, int n_in,
                              void* d_out, int out_size)
{
    const float* x         = (const float*)d_in[0];
    const float* W_in      = (const float*)d_in[1];
    const float* b_in      = (const float*)d_in[2];
    const float* W_msg     = (const float*)d_in[3];
    const float* rel_emb   = (const float*)d_in[4];
    const float* W_relproj = (const float*)d_in[5];
    const float* att_vec   = (const float*)d_in[6];
    const float* bias      = (const float*)d_in[7];
    const float* ln_g      = (const float*)d_in[8];
    const float* ln_b      = (const float*)d_in[9];
    const float* edge_attr = (const float*)d_in[10];
    const int*   edge_index= (const int*)d_in[11];
    const int*   edge_type = (const int*)d_in[12];
    float* out = (float*)d_out;

    int N = in_sizes[0] / INF;
    int E = in_sizes[12];
    int L = in_sizes[7] / H;
    const int* src = edge_index;
    const int* dst = edge_index + E;
    int nb = (N + 1023) / 1024;

    k_input<<<(N + 31) / 32, 256>>>(x, W_in, b_in, N);

    k_zero<<<(N + 255) / 256, 256>>>(N);
    k_hist<<<(E + 255) / 256, 256>>>(dst, E);
    k_scan1<<<nb, 1024>>>(N);
    k_scan2<<<1, 128>>>(nb);
    k_scan3<<<nb, 1024>>>(N);
    k_sortscatter<<<(E + 255) / 256, 256>>>(src, dst, edge_type, edge_attr, E);

    for (int l = 0; l < L; l++) {
        k_q<<<1, 256>>>(rel_emb + l * NREL * 16,
                        W_relproj + l * 16 * H,
                        att_vec + l * 3 * H);
        k_msg<<<(N + 63) / 64, 256>>>(W_msg + l * H * H,
                                      att_vec + l * 3 * H, N);
        k_w<<<(E + 255) / 256, 256>>>(E);
        k_aggr<<<(N * 32 + 255) / 256, 256>>>(bias + l * H,
                                              ln_g + l * H, ln_b + l * H,
                                              (l == L - 1) ? out : (float*)nullptr,
                                              N);
    }
}

// round 6
// speedup vs baseline: 1.4569x; 1.0352x over previous
#include <cuda_runtime.h>
#include <cuda_fp16.h>

#define H      64
#define INF    128
#define NREL   8
#define NMAX   100000
#define EMAX   1600000

__device__ __forceinline__ void fma4(float4& a, float s, const float4& w) {
    a.x += s * w.x; a.y += s * w.y; a.z += s * w.z; a.w += s * w.w;
}

// ---- scratch ----
__device__ __align__(128) float   g_h  [NMAX * H];
__device__ __align__(128) __half2 g_hmh[NMAX * (H / 2)];  // hm in fp16 (gather payload)
__device__ __align__(128) float g_ps [NMAX];
__device__ __align__(128) float g_pd [NMAX];
__device__ __align__(128) float g_q  [NREL];
__device__ __align__(128) unsigned g_srcs[EMAX];   // src | (typ<<20), dst-sorted
__device__ __align__(128) int      g_dsts[EMAX];   // dst per sorted edge
__device__ __align__(128) float    g_cf  [EMAX];   // 0.1*log(max(conf,1e-6))
__device__ __align__(128) float    g_ex  [EMAX];   // exp(e) per sorted edge
__device__ __align__(128) int g_deg [NMAX];
__device__ __align__(128) int g_cur [NMAX];
__device__ __align__(128) int g_off [NMAX + 1];
__device__ __align__(128) int g_bsum[128];
__device__ __align__(128) int g_boff[128];

// ---------------------------------------------------------------
// K0: h = relu(x @ W_in + b_in). 32-node tile; 2 nodes x 4 cols/thread.
// ---------------------------------------------------------------
__global__ __launch_bounds__(256) void k_input(
    const float* __restrict__ x, const float* __restrict__ W,
    const float* __restrict__ b, int N)
{
    __shared__ float Ws[INF * H];     // 32KB
    __shared__ float xs[32 * INF];    // 16KB
    int t = threadIdx.x;
    for (int j = t; j < INF * H / 4; j += 256)
        ((float4*)Ws)[j] = ((const float4*)W)[j];
    int n0 = blockIdx.x * 32;
    for (int j = t; j < 32 * INF / 4; j += 256) {
        int node = n0 + (j >> 5);
        float4 v = make_float4(0.f, 0.f, 0.f, 0.f);
        if (node < N) v = ((const float4*)x)[n0 * (INF / 4) + j];
        ((float4*)xs)[j] = v;
    }
    __syncthreads();
    int cg = t & 15;
    int rg = t >> 4;
    const float4* Wv = (const float4*)Ws;
    const float4* Xv = (const float4*)xs;
    float4 a0 = make_float4(0.f,0.f,0.f,0.f);
    float4 a1 = make_float4(0.f,0.f,0.f,0.f);
    #pragma unroll 8
    for (int k4 = 0; k4 < INF / 4; k4++) {
        float4 w0 = Wv[(k4*4+0)*16 + cg];
        float4 w1 = Wv[(k4*4+1)*16 + cg];
        float4 w2 = Wv[(k4*4+2)*16 + cg];
        float4 w3 = Wv[(k4*4+3)*16 + cg];
        float4 x0 = Xv[(rg*2+0)*32 + k4];
        float4 x1 = Xv[(rg*2+1)*32 + k4];
        fma4(a0, x0.x, w0); fma4(a0, x0.y, w1); fma4(a0, x0.z, w2); fma4(a0, x0.w, w3);
        fma4(a1, x1.x, w0); fma4(a1, x1.y, w1); fma4(a1, x1.z, w2); fma4(a1, x1.w, w3);
    }
    float4 bb = *(const float4*)&b[cg * 4];
    int node0 = n0 + rg * 2;
    if (node0 < N) {
        float4 o = make_float4(fmaxf(a0.x+bb.x,0.f), fmaxf(a0.y+bb.y,0.f),
                               fmaxf(a0.z+bb.z,0.f), fmaxf(a0.w+bb.w,0.f));
        *(float4*)&g_h[node0 * H + cg * 4] = o;
    }
    if (node0 + 1 < N) {
        float4 o = make_float4(fmaxf(a1.x+bb.x,0.f), fmaxf(a1.y+bb.y,0.f),
                               fmaxf(a1.z+bb.z,0.f), fmaxf(a1.w+bb.w,0.f));
        *(float4*)&g_h[(node0+1) * H + cg * 4] = o;
    }
}

// ---------------------------------------------------------------
// K1: hm = h @ W_msg (stored fp16); fused pd/ps (fp32).
// ---------------------------------------------------------------
__global__ __launch_bounds__(256) void k_msg(
    const float* __restrict__ Wm, const float* __restrict__ att, int N)
{
    __shared__ float Ws[H * H];    // 16KB
    __shared__ float hs[64 * H];   // 16KB
    int t = threadIdx.x;
    for (int j = t; j < H * H / 4; j += 256)
        ((float4*)Ws)[j] = ((const float4*)Wm)[j];
    int n0 = blockIdx.x * 64;
    for (int j = t; j < 64 * H / 4; j += 256) {
        int node = n0 + (j >> 4);
        float4 v = make_float4(0.f, 0.f, 0.f, 0.f);
        if (node < N) v = ((const float4*)g_h)[n0 * (H / 4) + j];
        ((float4*)hs)[j] = v;
    }
    __syncthreads();
    int cg = t & 15;
    int rg = t >> 4;
    const float4* Wv = (const float4*)Ws;
    const float4* Hv = (const float4*)hs;
    float4 acc[4];
    #pragma unroll
    for (int n = 0; n < 4; n++) acc[n] = make_float4(0.f,0.f,0.f,0.f);
    #pragma unroll 4
    for (int k4 = 0; k4 < H / 4; k4++) {
        float4 w0 = Wv[(k4*4+0)*16 + cg];
        float4 w1 = Wv[(k4*4+1)*16 + cg];
        float4 w2 = Wv[(k4*4+2)*16 + cg];
        float4 w3 = Wv[(k4*4+3)*16 + cg];
        #pragma unroll
        for (int n = 0; n < 4; n++) {
            float4 hv = Hv[(rg*4+n)*16 + k4];
            fma4(acc[n], hv.x, w0); fma4(acc[n], hv.y, w1);
            fma4(acc[n], hv.z, w2); fma4(acc[n], hv.w, w3);
        }
    }
    // store hm as fp16 (half2 pairs); lane cg covers half2 slots 2cg, 2cg+1
    #pragma unroll
    for (int n = 0; n < 4; n++) {
        int node = n0 + rg * 4 + n;
        if (node < N) {
            __half2 p0 = __floats2half2_rn(acc[n].x, acc[n].y);
            __half2 p1 = __floats2half2_rn(acc[n].z, acc[n].w);
            uint2 pk;
            pk.x = *(unsigned*)&p0;
            pk.y = *(unsigned*)&p1;
            *(uint2*)&g_hmh[node * (H/2) + cg * 2] = pk;
        }
    }
    // attention scalars from fp32 accumulators
    float4 ad = *(const float4*)&att[cg * 4];
    float4 as = *(const float4*)&att[H + cg * 4];
    float pdv[4], psv[4];
    #pragma unroll
    for (int n = 0; n < 4; n++) {
        pdv[n] = acc[n].x*ad.x + acc[n].y*ad.y + acc[n].z*ad.z + acc[n].w*ad.w;
        psv[n] = acc[n].x*as.x + acc[n].y*as.y + acc[n].z*as.z + acc[n].w*as.w;
    }
    #pragma unroll
    for (int o = 8; o; o >>= 1) {
        #pragma unroll
        for (int n = 0; n < 4; n++) {
            pdv[n] += __shfl_xor_sync(0xffffffffu, pdv[n], o);
            psv[n] += __shfl_xor_sync(0xffffffffu, psv[n], o);
        }
    }
    if (cg == 0) {
        #pragma unroll
        for (int n = 0; n < 4; n++) {
            int node = n0 + rg * 4 + n;
            if (node < N) { g_pd[node] = pdv[n]; g_ps[node] = psv[n]; }
        }
    }
}

// ---------------------------------------------------------------
// Kq: q[t] = (rel_emb[t] @ W_relproj) . a_rel
// ---------------------------------------------------------------
__global__ __launch_bounds__(256) void k_q(
    const float* __restrict__ rel, const float* __restrict__ Wp,
    const float* __restrict__ att)
{
    int warp = threadIdx.x >> 5, lane = threadIdx.x & 31;
    if (warp < NREL) {
        float acc = 0.f;
        for (int hh = lane; hh < H; hh += 32) {
            float v = 0.f;
            #pragma unroll
            for (int r = 0; r < 16; r++) v += rel[warp * 16 + r] * Wp[r * H + hh];
            acc += v * att[2 * H + hh];
        }
        #pragma unroll
        for (int o = 16; o; o >>= 1) acc += __shfl_xor_sync(0xffffffffu, acc, o);
        if (lane == 0) g_q[warp] = acc;
    }
}

// ---------------------------------------------------------------
// Preprocessing: counting sort of edges by dst (once per launch).
// ---------------------------------------------------------------
__global__ __launch_bounds__(256) void k_zero(int N)
{
    int i = blockIdx.x * blockDim.x + threadIdx.x;
    if (i < N) { g_deg[i] = 0; g_cur[i] = 0; }
}

__global__ __launch_bounds__(256) void k_hist(const int* __restrict__ dst, int E)
{
    int i = blockIdx.x * blockDim.x + threadIdx.x;
    if (i < E) atomicAdd(&g_deg[dst[i]], 1);
}

__global__ __launch_bounds__(1024) void k_scan1(int N)
{
    __shared__ int ws[32];
    int t = threadIdx.x, lane = t & 31, w = t >> 5;
    int i = blockIdx.x * 1024 + t;
    int v = (i < N) ? g_deg[i] : 0;
    #pragma unroll
    for (int o = 1; o < 32; o <<= 1) {
        int u = __shfl_up_sync(0xffffffffu, v, o);
        if (lane >= o) v += u;
    }
    if (lane == 31) ws[w] = v;
    __syncthreads();
    if (w == 0) {
        int bsum = ws[lane];
        #pragma unroll
        for (int o = 1; o < 32; o <<= 1) {
            int u = __shfl_up_sync(0xffffffffu, bsum, o);
            if (lane >= o) bsum += u;
        }
        ws[lane] = bsum;
    }
    __syncthreads();
    if (w) v += ws[w - 1];
    if (i < N) g_off[i + 1] = v;
    if (t == 1023) g_bsum[blockIdx.x] = v;
}

__global__ __launch_bounds__(128) void k_scan2(int nb)
{
    __shared__ int s[128];
    int t = threadIdx.x;
    s[t] = (t < nb) ? g_bsum[t] : 0;
    __syncthreads();
    #pragma unroll
    for (int o = 1; o < 128; o <<= 1) {
        int v = (t >= o) ? s[t - o] : 0;
        __syncthreads();
        s[t] += v;
        __syncthreads();
    }
    if (t < nb) g_boff[t] = t ? s[t - 1] : 0;
}

__global__ __launch_bounds__(1024) void k_scan3(int N)
{
    int i = blockIdx.x * 1024 + threadIdx.x;
    if (i < N) g_off[i + 1] += g_boff[blockIdx.x];
    if (i == 0) g_off[0] = 0;
}

__global__ __launch_bounds__(256) void k_sortscatter(
    const int* __restrict__ src, const int* __restrict__ dst,
    const int* __restrict__ typ, const float* __restrict__ conf, int E)
{
    int i = blockIdx.x * blockDim.x + threadIdx.x;
    if (i >= E) return;
    int d = dst[i];
    int pos = g_off[d] + atomicAdd(&g_cur[d], 1);
    int t = min(max(typ[i], 0), NREL - 1);
    g_srcs[pos] = (unsigned)src[i] | ((unsigned)t << 20);
    g_dsts[pos] = d;
    g_cf[pos]   = 0.1f * __logf(fmaxf(conf[i], 1e-6f));
}

// ---------------------------------------------------------------
// K_w: edge-parallel coalesced logit + exp over sorted edges.
// ---------------------------------------------------------------
__global__ __launch_bounds__(256) void k_w(int E)
{
    int i = blockIdx.x * blockDim.x + threadIdx.x;
    if (i >= E) return;
    unsigned p = g_srcs[i];
    int d = g_dsts[i];
    float e = g_pd[d] + g_ps[p & 0xFFFFF] + g_q[p >> 20];
    e = e > 0.f ? e : 0.2f * e;
    e += g_cf[i];
    g_ex[i] = __expf(e);
}

// ---------------------------------------------------------------
// K_aggr: warp-per-node gather-sum (fp16 payload, fp32 accum), fused
// softmax normalization + residual + relu + layernorm.
// ---------------------------------------------------------------
__global__ __launch_bounds__(256) void k_aggr(
    const float* __restrict__ bias, const float* __restrict__ lng,
    const float* __restrict__ lnb, float* __restrict__ hout, int N)
{
    int n = (blockIdx.x * blockDim.x + threadIdx.x) >> 5;
    if (n >= N) return;
    int lane = threadIdx.x & 31;
    int half = lane >> 4;
    int l    = lane & 15;
    int beg = g_off[n], end = g_off[n + 1];
    float4 acc = make_float4(0.f, 0.f, 0.f, 0.f);
    float ssum = 0.f;
    int j = beg + half;
    for (; j + 2 < end; j += 4) {
        unsigned p0 = g_srcs[j];
        unsigned p1 = g_srcs[j + 2];
        float e0 = g_ex[j];
        float e1 = g_ex[j + 2];
        uint2 r0 = *(const uint2*)&g_hmh[(p0 & 0xFFFFF) * (H/2) + l * 2];
        uint2 r1 = *(const uint2*)&g_hmh[(p1 & 0xFFFFF) * (H/2) + l * 2];
        float2 a0 = __half22float2(*(__half2*)&r0.x);
        float2 b0 = __half22float2(*(__half2*)&r0.y);
        float2 a1 = __half22float2(*(__half2*)&r1.x);
        float2 b1 = __half22float2(*(__half2*)&r1.y);
        acc.x += e0 * a0.x + e1 * a1.x;
        acc.y += e0 * a0.y + e1 * a1.y;
        acc.z += e0 * b0.x + e1 * b1.x;
        acc.w += e0 * b0.y + e1 * b1.y;
        ssum += e0 + e1;
    }
    for (; j < end; j += 2) {
        unsigned p = g_srcs[j];
        float e0 = g_ex[j];
        uint2 r = *(const uint2*)&g_hmh[(p & 0xFFFFF) * (H/2) + l * 2];
        float2 a = __half22float2(*(__half2*)&r.x);
        float2 b = __half22float2(*(__half2*)&r.y);
        acc.x += e0 * a.x; acc.y += e0 * a.y;
        acc.z += e0 * b.x; acc.w += e0 * b.y;
        ssum += e0;
    }
    acc.x += __shfl_xor_sync(0xffffffffu, acc.x, 16);
    acc.y += __shfl_xor_sync(0xffffffffu, acc.y, 16);
    acc.z += __shfl_xor_sync(0xffffffffu, acc.z, 16);
    acc.w += __shfl_xor_sync(0xffffffffu, acc.w, 16);
    ssum  += __shfl_xor_sync(0xffffffffu, ssum,  16);
    float inv = (ssum > 0.f) ? (1.f / ssum) : 0.f;
    float4 hv = *(const float4*)&g_h[n * H + l * 4];
    float4 bb = *(const float4*)&bias[l * 4];
    float4 u;
    u.x = hv.x + fmaxf(acc.x * inv + bb.x, 0.f);
    u.y = hv.y + fmaxf(acc.y * inv + bb.y, 0.f);
    u.z = hv.z + fmaxf(acc.z * inv + bb.z, 0.f);
    u.w = hv.w + fmaxf(acc.w * inv + bb.w, 0.f);
    float s = u.x + u.y + u.z + u.w;
    #pragma unroll
    for (int o = 16; o; o >>= 1) s += __shfl_xor_sync(0xffffffffu, s, o);
    float mu = s * (1.f / 128.f);
    float4 d4 = make_float4(u.x - mu, u.y - mu, u.z - mu, u.w - mu);
    float vs = d4.x*d4.x + d4.y*d4.y + d4.z*d4.z + d4.w*d4.w;
    #pragma unroll
    for (int o = 16; o; o >>= 1) vs += __shfl_xor_sync(0xffffffffu, vs, o);
    float invs = rsqrtf(vs * (1.f / 128.f) + 1e-5f);
    if (half == 0) {
        float4 g4 = *(const float4*)&lng[l * 4];
        float4 b2 = *(const float4*)&lnb[l * 4];
        float* outp = hout ? hout : g_h;
        float4 o4;
        o4.x = d4.x * invs * g4.x + b2.x;
        o4.y = d4.y * invs * g4.y + b2.y;
        o4.z = d4.z * invs * g4.z + b2.z;
        o4.w = d4.w * invs * g4.w + b2.w;
        *(float4*)&outp[n * H + l * 4] = o4;
    }
}

// ---------------------------------------------------------------
extern "C" void kernel_launch(void* const* d_in, const int* in_sizes, int n_in,
                              void* d_out, int out_size)
{
    const float* x         = (const float*)d_in[0];
    const float* W_in      = (const float*)d_in[1];
    const float* b_in      = (const float*)d_in[2];
    const float* W_msg     = (const float*)d_in[3];
    const float* rel_emb   = (const float*)d_in[4];
    const float* W_relproj = (const float*)d_in[5];
    const float* att_vec   = (const float*)d_in[6];
    const float* bias      = (const float*)d_in[7];
    const float* ln_g      = (const float*)d_in[8];
    const float* ln_b      = (const float*)d_in[9];
    const float* edge_attr = (const float*)d_in[10];
    const int*   edge_index= (const int*)d_in[11];
    const int*   edge_type = (const int*)d_in[12];
    float* out = (float*)d_out;

    int N = in_sizes[0] / INF;
    int E = in_sizes[12];
    int L = in_sizes[7] / H;
    const int* src = edge_index;
    const int* dst = edge_index + E;
    int nb = (N + 1023) / 1024;

    k_input<<<(N + 31) / 32, 256>>>(x, W_in, b_in, N);

    k_zero<<<(N + 255) / 256, 256>>>(N);
    k_hist<<<(E + 255) / 256, 256>>>(dst, E);
    k_scan1<<<nb, 1024>>>(N);
    k_scan2<<<1, 128>>>(nb);
    k_scan3<<<nb, 1024>>>(N);
    k_sortscatter<<<(E + 255) / 256, 256>>>(src, dst, edge_type, edge_attr, E);

    for (int l = 0; l < L; l++) {
        k_q<<<1, 256>>>(rel_emb + l * NREL * 16,
                        W_relproj + l * 16 * H,
                        att_vec + l * 3 * H);
        k_msg<<<(N + 63) / 64, 256>>>(W_msg + l * H * H,
                                      att_vec + l * 3 * H, N);
        k_w<<<(E + 255) / 256, 256>>>(E);
        k_aggr<<<(N * 32 + 255) / 256, 256>>>(bias + l * H,
                                              ln_g + l * H, ln_b + l * H,
                                              (l == L - 1) ? out : (float*)nullptr,
                                              N);
    }
}

// round 8
// speedup vs baseline: 1.5298x; 1.0501x over previous
#include <cuda_runtime.h>
#include <cuda_fp16.h>
#include <mma.h>

using namespace nvcuda;

#define H      64
#define INF    128
#define NREL   8
#define NMAX   100000
#define EMAX   1600000

// ---- scratch ----
__device__ __align__(128) float   g_h  [NMAX * H];
__device__ __align__(128) __half2 g_hmh[NMAX * (H / 2)];  // hm in fp16 (gather payload)
__device__ __align__(128) float g_ps [NMAX];
__device__ __align__(128) float g_pd [NMAX];
__device__ __align__(128) float g_q  [NREL];
__device__ __align__(128) unsigned g_srcs[EMAX];   // src | (typ<<20), dst-sorted
__device__ __align__(128) int      g_dsts[EMAX];
__device__ __align__(128) float    g_cf  [EMAX];
__device__ __align__(128) float    g_ex  [EMAX];
__device__ __align__(128) int g_deg [NMAX];
__device__ __align__(128) int g_cur [NMAX];
__device__ __align__(128) int g_off [NMAX + 1];
__device__ __align__(128) int g_bsum[128];
__device__ __align__(128) int g_boff[128];

#define LDA 72   // fp16 leading dim for A tiles (pad vs 64 to break conflicts)

// ---------------------------------------------------------------
// K0 (WMMA): h = relu(x @ W_in + b_in). M-tile 128 nodes, K=128 in
// two 64-wide passes accumulating in fragments. 8 warps, 4 n-tiles each.
// ---------------------------------------------------------------
__global__ __launch_bounds__(256) void k_input_mma(
    const float* __restrict__ x, const float* __restrict__ W,
    const float* __restrict__ b, int N)
{
    // overlay: phase1 As(18432) + Bs(8192) = 26624; phase2 Cs(32768)
    __shared__ __align__(128) char sm[32768];
    __half* As = (__half*)sm;               // [128][LDA]
    __half* Bs = (__half*)(sm + 18432);     // [64][64] row-major (k,n)
    float*  Cs = (float*)sm;                // [128][64]

    int t = threadIdx.x, w = t >> 5;
    int n0 = blockIdx.x * 128;

    wmma::fragment<wmma::accumulator, 16, 16, 16, float> acc[4];
    #pragma unroll
    for (int nt = 0; nt < 4; nt++) wmma::fill_fragment(acc[nt], 0.f);

    for (int p = 0; p < 2; p++) {
        __syncthreads();
        // A: 128 rows x 64 cols (cols 64p..) fp16
        for (int i = t; i < 128 * 16; i += 256) {
            int r = i >> 4, c4 = i & 15;
            int node = n0 + r;
            float4 v = make_float4(0.f, 0.f, 0.f, 0.f);
            if (node < N) v = *(const float4*)&x[node * INF + p * 64 + c4 * 4];
            __half2 h0 = __floats2half2_rn(v.x, v.y);
            __half2 h1 = __floats2half2_rn(v.z, v.w);
            uint2 pk; pk.x = *(unsigned*)&h0; pk.y = *(unsigned*)&h1;
            *(uint2*)&As[r * LDA + c4 * 4] = pk;
        }
        // B: rows k=0..63 (global k=64p+k), cols n=0..63
        for (int i = t; i < 64 * 16; i += 256) {
            int k = i >> 4, c4 = i & 15;
            float4 v = *(const float4*)&W[(p * 64 + k) * 64 + c4 * 4];
            __half2 h0 = __floats2half2_rn(v.x, v.y);
            __half2 h1 = __floats2half2_rn(v.z, v.w);
            uint2 pk; pk.x = *(unsigned*)&h0; pk.y = *(unsigned*)&h1;
            *(uint2*)&Bs[k * 64 + c4 * 4] = pk;
        }
        __syncthreads();
        #pragma unroll
        for (int ks = 0; ks < 4; ks++) {
            wmma::fragment<wmma::matrix_a, 16, 16, 16, __half, wmma::row_major> af;
            wmma::load_matrix_sync(af, As + (w * 16) * LDA + ks * 16, LDA);
            #pragma unroll
            for (int nt = 0; nt < 4; nt++) {
                wmma::fragment<wmma::matrix_b, 16, 16, 16, __half, wmma::row_major> bf;
                wmma::load_matrix_sync(bf, Bs + (ks * 16) * 64 + nt * 16, 64);
                wmma::mma_sync(acc[nt], af, bf, acc[nt]);
            }
        }
    }
    __syncthreads();
    #pragma unroll
    for (int nt = 0; nt < 4; nt++)
        wmma::store_matrix_sync(Cs + (w * 16) * 64 + nt * 16, acc[nt], 64,
                                wmma::mem_row_major);
    __syncthreads();
    for (int i = t; i < 128 * 16; i += 256) {
        int r = i >> 4, c4 = i & 15;
        int node = n0 + r;
        if (node < N) {
            float4 v = *(float4*)&Cs[r * 64 + c4 * 4];
            float4 bb = *(const float4*)&b[c4 * 4];
            float4 o;
            o.x = fmaxf(v.x + bb.x, 0.f);
            o.y = fmaxf(v.y + bb.y, 0.f);
            o.z = fmaxf(v.z + bb.z, 0.f);
            o.w = fmaxf(v.w + bb.w, 0.f);
            *(float4*)&g_h[node * H + c4 * 4] = o;
        }
    }
}

// ---------------------------------------------------------------
// K1 (WMMA): hm = h @ W_msg (fp16 out) + fused pd/ps. M-tile 128, K=64.
// ---------------------------------------------------------------
__global__ __launch_bounds__(256) void k_msg_mma(
    const float* __restrict__ Wm, const float* __restrict__ att, int N)
{
    __shared__ __align__(128) char sm[32768];
    __half* As = (__half*)sm;               // [128][LDA]
    __half* Bs = (__half*)(sm + 18432);     // [64][64]
    float*  Cs = (float*)sm;                // [128][64]

    int t = threadIdx.x, w = t >> 5, lane = t & 31;
    int n0 = blockIdx.x * 128;

    // A from g_h
    for (int i = t; i < 128 * 16; i += 256) {
        int r = i >> 4, c4 = i & 15;
        int node = n0 + r;
        float4 v = make_float4(0.f, 0.f, 0.f, 0.f);
        if (node < N) v = *(const float4*)&g_h[node * H + c4 * 4];
        __half2 h0 = __floats2half2_rn(v.x, v.y);
        __half2 h1 = __floats2half2_rn(v.z, v.w);
        uint2 pk; pk.x = *(unsigned*)&h0; pk.y = *(unsigned*)&h1;
        *(uint2*)&As[r * LDA + c4 * 4] = pk;
    }
    // B = W_msg [k][n] row-major
    for (int i = t; i < 64 * 16; i += 256) {
        int k = i >> 4, c4 = i & 15;
        float4 v = *(const float4*)&Wm[k * 64 + c4 * 4];
        __half2 h0 = __floats2half2_rn(v.x, v.y);
        __half2 h1 = __floats2half2_rn(v.z, v.w);
        uint2 pk; pk.x = *(unsigned*)&h0; pk.y = *(unsigned*)&h1;
        *(uint2*)&Bs[k * 64 + c4 * 4] = pk;
    }
    __syncthreads();

    wmma::fragment<wmma::accumulator, 16, 16, 16, float> acc[4];
    #pragma unroll
    for (int nt = 0; nt < 4; nt++) wmma::fill_fragment(acc[nt], 0.f);
    #pragma unroll
    for (int ks = 0; ks < 4; ks++) {
        wmma::fragment<wmma::matrix_a, 16, 16, 16, __half, wmma::row_major> af;
        wmma::load_matrix_sync(af, As + (w * 16) * LDA + ks * 16, LDA);
        #pragma unroll
        for (int nt = 0; nt < 4; nt++) {
            wmma::fragment<wmma::matrix_b, 16, 16, 16, __half, wmma::row_major> bf;
            wmma::load_matrix_sync(bf, Bs + (ks * 16) * 64 + nt * 16, 64);
            wmma::mma_sync(acc[nt], af, bf, acc[nt]);
        }
    }
    __syncthreads();
    #pragma unroll
    for (int nt = 0; nt < 4; nt++)
        wmma::store_matrix_sync(Cs + (w * 16) * 64 + nt * 16, acc[nt], 64,
                                wmma::mem_row_major);
    __syncthreads();

    // epilogue: per-row pd/ps + fp16 hm store. warp w owns rows w*16..w*16+15.
    float ad0 = att[lane],      ad1 = att[lane + 32];
    float as0 = att[64 + lane], as1 = att[96 + lane];
    for (int rr = 0; rr < 16; rr++) {
        int r = w * 16 + rr;
        int node = n0 + r;
        float v0 = Cs[r * 64 + lane];
        float v1 = Cs[r * 64 + 32 + lane];
        float pd = v0 * ad0 + v1 * ad1;
        float ps = v0 * as0 + v1 * as1;
        #pragma unroll
        for (int o = 16; o; o >>= 1) {
            pd += __shfl_xor_sync(0xffffffffu, pd, o);
            ps += __shfl_xor_sync(0xffffffffu, ps, o);
        }
        float u0 = Cs[r * 64 + 2 * lane];
        float u1 = Cs[r * 64 + 2 * lane + 1];
        if (node < N) {
            g_hmh[node * (H / 2) + lane] = __floats2half2_rn(u0, u1);
            if (lane == 0) { g_pd[node] = pd; g_ps[node] = ps; }
        }
    }
}

// ---------------------------------------------------------------
// Kq: q[t] = (rel_emb[t] @ W_relproj) . a_rel
// ---------------------------------------------------------------
__global__ __launch_bounds__(256) void k_q(
    const float* __restrict__ rel, const float* __restrict__ Wp,
    const float* __restrict__ att)
{
    int warp = threadIdx.x >> 5, lane = threadIdx.x & 31;
    if (warp < NREL) {
        float acc = 0.f;
        for (int hh = lane; hh < H; hh += 32) {
            float v = 0.f;
            #pragma unroll
            for (int r = 0; r < 16; r++) v += rel[warp * 16 + r] * Wp[r * H + hh];
            acc += v * att[2 * H + hh];
        }
        #pragma unroll
        for (int o = 16; o; o >>= 1) acc += __shfl_xor_sync(0xffffffffu, acc, o);
        if (lane == 0) g_q[warp] = acc;
    }
}

// ---------------------------------------------------------------
// Counting sort of edges by dst (once per launch)
// ---------------------------------------------------------------
__global__ __launch_bounds__(256) void k_zero(int N)
{
    int i = blockIdx.x * blockDim.x + threadIdx.x;
    if (i < N) { g_deg[i] = 0; g_cur[i] = 0; }
}

__global__ __launch_bounds__(256) void k_hist(const int* __restrict__ dst, int E)
{
    int i = blockIdx.x * blockDim.x + threadIdx.x;
    if (i < E) atomicAdd(&g_deg[dst[i]], 1);
}

__global__ __launch_bounds__(1024) void k_scan1(int N)
{
    __shared__ int ws[32];
    int t = threadIdx.x, lane = t & 31, w = t >> 5;
    int i = blockIdx.x * 1024 + t;
    int v = (i < N) ? g_deg[i] : 0;
    #pragma unroll
    for (int o = 1; o < 32; o <<= 1) {
        int u = __shfl_up_sync(0xffffffffu, v, o);
        if (lane >= o) v += u;
    }
    if (lane == 31) ws[w] = v;
    __syncthreads();
    if (w == 0) {
        int bsum = ws[lane];
        #pragma unroll
        for (int o = 1; o < 32; o <<= 1) {
            int u = __shfl_up_sync(0xffffffffu, bsum, o);
            if (lane >= o) bsum += u;
        }
        ws[lane] = bsum;
    }
    __syncthreads();
    if (w) v += ws[w - 1];
    if (i < N) g_off[i + 1] = v;
    if (t == 1023) g_bsum[blockIdx.x] = v;
}

__global__ __launch_bounds__(128) void k_scan2(int nb)
{
    __shared__ int s[128];
    int t = threadIdx.x;
    s[t] = (t < nb) ? g_bsum[t] : 0;
    __syncthreads();
    #pragma unroll
    for (int o = 1; o < 128; o <<= 1) {
        int v = (t >= o) ? s[t - o] : 0;
        __syncthreads();
        s[t] += v;
        __syncthreads();
    }
    if (t < nb) g_boff[t] = t ? s[t - 1] : 0;
}

__global__ __launch_bounds__(1024) void k_scan3(int N)
{
    int i = blockIdx.x * 1024 + threadIdx.x;
    if (i < N) g_off[i + 1] += g_boff[blockIdx.x];
    if (i == 0) g_off[0] = 0;
}

__global__ __launch_bounds__(256) void k_sortscatter(
    const int* __restrict__ src, const int* __restrict__ dst,
    const int* __restrict__ typ, const float* __restrict__ conf, int E)
{
    int i = blockIdx.x * blockDim.x + threadIdx.x;
    if (i >= E) return;
    int d = dst[i];
    int pos = g_off[d] + atomicAdd(&g_cur[d], 1);
    int t = min(max(typ[i], 0), NREL - 1);
    g_srcs[pos] = (unsigned)src[i] | ((unsigned)t << 20);
    g_dsts[pos] = d;
    g_cf[pos]   = 0.1f * __logf(fmaxf(conf[i], 1e-6f));
}

// ---------------------------------------------------------------
// K_w: edge-parallel coalesced logit + exp
// ---------------------------------------------------------------
__global__ __launch_bounds__(256) void k_w(int E)
{
    int i = blockIdx.x * blockDim.x + threadIdx.x;
    if (i >= E) return;
    unsigned p = g_srcs[i];
    int d = g_dsts[i];
    float e = g_pd[d] + g_ps[p & 0xFFFFF] + g_q[p >> 20];
    e = e > 0.f ? e : 0.2f * e;
    e += g_cf[i];
    g_ex[i] = __expf(e);
}

// ---------------------------------------------------------------
// K_aggr: warp-per-node gather-sum (fp16 payload, fp32 accum), fused
// softmax normalization + residual + relu + layernorm.
// ---------------------------------------------------------------
__global__ __launch_bounds__(256) void k_aggr(
    const float* __restrict__ bias, const float* __restrict__ lng,
    const float* __restrict__ lnb, float* __restrict__ hout, int N)
{
    int n = (blockIdx.x * blockDim.x + threadIdx.x) >> 5;
    if (n >= N) return;
    int lane = threadIdx.x & 31;
    int half = lane >> 4;
    int l    = lane & 15;
    int beg = g_off[n], end = g_off[n + 1];
    float4 acc = make_float4(0.f, 0.f, 0.f, 0.f);
    float ssum = 0.f;
    int j = beg + half;
    for (; j + 2 < end; j += 4) {
        unsigned p0 = g_srcs[j];
        unsigned p1 = g_srcs[j + 2];
        float e0 = g_ex[j];
        float e1 = g_ex[j + 2];
        uint2 r0 = *(const uint2*)&g_hmh[(p0 & 0xFFFFF) * (H/2) + l * 2];
        uint2 r1 = *(const uint2*)&g_hmh[(p1 & 0xFFFFF) * (H/2) + l * 2];
        float2 a0 = __half22float2(*(__half2*)&r0.x);
        float2 b0 = __half22float2(*(__half2*)&r0.y);
        float2 a1 = __half22float2(*(__half2*)&r1.x);
        float2 b1 = __half22float2(*(__half2*)&r1.y);
        acc.x += e0 * a0.x + e1 * a1.x;
        acc.y += e0 * a0.y + e1 * a1.y;
        acc.z += e0 * b0.x + e1 * b1.x;
        acc.w += e0 * b0.y + e1 * b1.y;
        ssum += e0 + e1;
    }
    for (; j < end; j += 2) {
        unsigned p = g_srcs[j];
        float e0 = g_ex[j];
        uint2 r = *(const uint2*)&g_hmh[(p & 0xFFFFF) * (H/2) + l * 2];
        float2 a = __half22float2(*(__half2*)&r.x);
        float2 b = __half22float2(*(__half2*)&r.y);
        acc.x += e0 * a.x; acc.y += e0 * a.y;
        acc.z += e0 * b.x; acc.w += e0 * b.y;
        ssum += e0;
    }
    acc.x += __shfl_xor_sync(0xffffffffu, acc.x, 16);
    acc.y += __shfl_xor_sync(0xffffffffu, acc.y, 16);
    acc.z += __shfl_xor_sync(0xffffffffu, acc.z, 16);
    acc.w += __shfl_xor_sync(0xffffffffu, acc.w, 16);
    ssum  += __shfl_xor_sync(0xffffffffu, ssum,  16);
    float inv = (ssum > 0.f) ? (1.f / ssum) : 0.f;
    float4 hv = *(const float4*)&g_h[n * H + l * 4];
    float4 bb = *(const float4*)&bias[l * 4];
    float4 u;
    u.x = hv.x + fmaxf(acc.x * inv + bb.x, 0.f);
    u.y = hv.y + fmaxf(acc.y * inv + bb.y, 0.f);
    u.z = hv.z + fmaxf(acc.z * inv + bb.z, 0.f);
    u.w = hv.w + fmaxf(acc.w * inv + bb.w, 0.f);
    float s = u.x + u.y + u.z + u.w;
    #pragma unroll
    for (int o = 16; o; o >>= 1) s += __shfl_xor_sync(0xffffffffu, s, o);
    float mu = s * (1.f / 128.f);
    float4 d4 = make_float4(u.x - mu, u.y - mu, u.z - mu, u.w - mu);
    float vs = d4.x*d4.x + d4.y*d4.y + d4.z*d4.z + d4.w*d4.w;
    #pragma unroll
    for (int o = 16; o; o >>= 1) vs += __shfl_xor_sync(0xffffffffu, vs, o);
    float invs = rsqrtf(vs * (1.f / 128.f) + 1e-5f);
    if (half == 0) {
        float4 g4 = *(const float4*)&lng[l * 4];
        float4 b2 = *(const float4*)&lnb[l * 4];
        float* outp = hout ? hout : g_h;
        float4 o4;
        o4.x = d4.x * invs * g4.x + b2.x;
        o4.y = d4.y * invs * g4.y + b2.y;
        o4.z = d4.z * invs * g4.z + b2.z;
        o4.w = d4.w * invs * g4.w + b2.w;
        *(float4*)&outp[n * H + l * 4] = o4;
    }
}

// ---------------------------------------------------------------
extern "C" void kernel_launch(void* const* d_in, const int* in_sizes, int n_in,
                              void* d_out, int out_size)
{
    const float* x         = (const float*)d_in[0];
    const float* W_in      = (const float*)d_in[1];
    const float* b_in      = (const float*)d_in[2];
    const float* W_msg     = (const float*)d_in[3];
    const float* rel_emb   = (const float*)d_in[4];
    const float* W_relproj = (const float*)d_in[5];
    const float* att_vec   = (const float*)d_in[6];
    const float* bias      = (const float*)d_in[7];
    const float* ln_g      = (const float*)d_in[8];
    const float* ln_b      = (const float*)d_in[9];
    const float* edge_attr = (const float*)d_in[10];
    const int*   edge_index= (const int*)d_in[11];
    const int*   edge_type = (const int*)d_in[12];
    float* out = (float*)d_out;

    int N = in_sizes[0] / INF;
    int E = in_sizes[12];
    int L = in_sizes[7] / H;
    const int* src = edge_index;
    const int* dst = edge_index + E;
    int nb = (N + 1023) / 1024;

    k_input_mma<<<(N + 127) / 128, 256>>>(x, W_in, b_in, N);

    k_zero<<<(N + 255) / 256, 256>>>(N);
    k_hist<<<(E + 255) / 256, 256>>>(dst, E);
    k_scan1<<<nb, 1024>>>(N);
    k_scan2<<<1, 128>>>(nb);
    k_scan3<<<nb, 1024>>>(N);
    k_sortscatter<<<(E + 255) / 256, 256>>>(src, dst, edge_type, edge_attr, E);

    for (int l = 0; l < L; l++) {
        k_q<<<1, 256>>>(rel_emb + l * NREL * 16,
                        W_relproj + l * 16 * H,
                        att_vec + l * 3 * H);
        k_msg_mma<<<(N + 127) / 128, 256>>>(W_msg + l * H * H,
                                            att_vec + l * 3 * H, N);
        k_w<<<(E + 255) / 256, 256>>>(E);
        k_aggr<<<(N * 32 + 255) / 256, 256>>>(bias + l * H,
                                              ln_g + l * H, ln_b + l * H,
                                              (l == L - 1) ? out : (float*)nullptr,
                                              N);
    }
}

// round 9
// speedup vs baseline: 1.6283x; 1.0644x over previous
#include <cuda_runtime.h>
#include <cuda_fp16.h>
#include <mma.h>

using namespace nvcuda;

#define H      64
#define INF    128
#define NREL   8
#define NMAX   100000
#define EMAX   1600000

// ---- scratch ----
__device__ __align__(128) float   g_h  [NMAX * H];
__device__ __align__(128) __half2 g_hmh[NMAX * (H / 2)];  // hm in fp16 (gather payload)
__device__ __align__(128) float g_ps [NMAX];
__device__ __align__(128) float g_pd [NMAX];
__device__ __align__(128) float g_q  [NREL];
__device__ __align__(128) unsigned g_srcs[EMAX + 8];   // src | (typ<<20), dst-sorted (+pad for prefetch)
__device__ __align__(128) int      g_dsts[EMAX];
__device__ __align__(128) float    g_cf  [EMAX];
__device__ __align__(128) float    g_ex  [EMAX + 8];   // exp(e), (+pad for prefetch)
__device__ __align__(128) int g_deg [NMAX];
__device__ __align__(128) int g_cur [NMAX];
__device__ __align__(128) int g_off [NMAX + 1];
__device__ __align__(128) int g_bsum[128];

#define LDA 72   // fp16 leading dim for A tiles (pad vs 64 to break conflicts)

// ---------------------------------------------------------------
// K0 (WMMA): h = relu(x @ W_in + b_in); also zeroes deg/cur slice.
// ---------------------------------------------------------------
__global__ __launch_bounds__(256) void k_input_mma(
    const float* __restrict__ x, const float* __restrict__ W,
    const float* __restrict__ b, int N)
{
    __shared__ __align__(128) char sm[32768];
    __half* As = (__half*)sm;               // [128][LDA]
    __half* Bs = (__half*)(sm + 18432);     // [64][64] row-major (k,n)
    float*  Cs = (float*)sm;                // [128][64]

    int t = threadIdx.x, w = t >> 5;
    int n0 = blockIdx.x * 128;

    // fused: zero sort counters for this block's node slice
    if (t < 128 && n0 + t < N) { g_deg[n0 + t] = 0; g_cur[n0 + t] = 0; }

    wmma::fragment<wmma::accumulator, 16, 16, 16, float> acc[4];
    #pragma unroll
    for (int nt = 0; nt < 4; nt++) wmma::fill_fragment(acc[nt], 0.f);

    for (int p = 0; p < 2; p++) {
        __syncthreads();
        for (int i = t; i < 128 * 16; i += 256) {
            int r = i >> 4, c4 = i & 15;
            int node = n0 + r;
            float4 v = make_float4(0.f, 0.f, 0.f, 0.f);
            if (node < N) v = *(const float4*)&x[node * INF + p * 64 + c4 * 4];
            __half2 h0 = __floats2half2_rn(v.x, v.y);
            __half2 h1 = __floats2half2_rn(v.z, v.w);
            uint2 pk; pk.x = *(unsigned*)&h0; pk.y = *(unsigned*)&h1;
            *(uint2*)&As[r * LDA + c4 * 4] = pk;
        }
        for (int i = t; i < 64 * 16; i += 256) {
            int k = i >> 4, c4 = i & 15;
            float4 v = *(const float4*)&W[(p * 64 + k) * 64 + c4 * 4];
            __half2 h0 = __floats2half2_rn(v.x, v.y);
            __half2 h1 = __floats2half2_rn(v.z, v.w);
            uint2 pk; pk.x = *(unsigned*)&h0; pk.y = *(unsigned*)&h1;
            *(uint2*)&Bs[k * 64 + c4 * 4] = pk;
        }
        __syncthreads();
        #pragma unroll
        for (int ks = 0; ks < 4; ks++) {
            wmma::fragment<wmma::matrix_a, 16, 16, 16, __half, wmma::row_major> af;
            wmma::load_matrix_sync(af, As + (w * 16) * LDA + ks * 16, LDA);
            #pragma unroll
            for (int nt = 0; nt < 4; nt++) {
                wmma::fragment<wmma::matrix_b, 16, 16, 16, __half, wmma::row_major> bf;
                wmma::load_matrix_sync(bf, Bs + (ks * 16) * 64 + nt * 16, 64);
                wmma::mma_sync(acc[nt], af, bf, acc[nt]);
            }
        }
    }
    __syncthreads();
    #pragma unroll
    for (int nt = 0; nt < 4; nt++)
        wmma::store_matrix_sync(Cs + (w * 16) * 64 + nt * 16, acc[nt], 64,
                                wmma::mem_row_major);
    __syncthreads();
    for (int i = t; i < 128 * 16; i += 256) {
        int r = i >> 4, c4 = i & 15;
        int node = n0 + r;
        if (node < N) {
            float4 v = *(float4*)&Cs[r * 64 + c4 * 4];
            float4 bb = *(const float4*)&b[c4 * 4];
            float4 o;
            o.x = fmaxf(v.x + bb.x, 0.f);
            o.y = fmaxf(v.y + bb.y, 0.f);
            o.z = fmaxf(v.z + bb.z, 0.f);
            o.w = fmaxf(v.w + bb.w, 0.f);
            *(float4*)&g_h[node * H + c4 * 4] = o;
        }
    }
}

// ---------------------------------------------------------------
// K1 (WMMA): hm = h @ W_msg (fp16 out) + fused pd/ps + fused q (block 0).
// ---------------------------------------------------------------
__global__ __launch_bounds__(256) void k_msg_mma(
    const float* __restrict__ Wm, const float* __restrict__ att,
    const float* __restrict__ rel, const float* __restrict__ Wp, int N)
{
    __shared__ __align__(128) char sm[32768];
    __half* As = (__half*)sm;               // [128][LDA]
    __half* Bs = (__half*)(sm + 18432);     // [64][64]
    float*  Cs = (float*)sm;                // [128][64]

    int t = threadIdx.x, w = t >> 5, lane = t & 31;
    int n0 = blockIdx.x * 128;

    // fused k_q: block 0's warps compute per-relation scalar
    if (blockIdx.x == 0 && w < NREL) {
        float acc = 0.f;
        for (int hh = lane; hh < H; hh += 32) {
            float v = 0.f;
            #pragma unroll
            for (int r = 0; r < 16; r++) v += rel[w * 16 + r] * Wp[r * H + hh];
            acc += v * att[2 * H + hh];
        }
        #pragma unroll
        for (int o = 16; o; o >>= 1) acc += __shfl_xor_sync(0xffffffffu, acc, o);
        if (lane == 0) g_q[w] = acc;
    }

    for (int i = t; i < 128 * 16; i += 256) {
        int r = i >> 4, c4 = i & 15;
        int node = n0 + r;
        float4 v = make_float4(0.f, 0.f, 0.f, 0.f);
        if (node < N) v = *(const float4*)&g_h[node * H + c4 * 4];
        __half2 h0 = __floats2half2_rn(v.x, v.y);
        __half2 h1 = __floats2half2_rn(v.z, v.w);
        uint2 pk; pk.x = *(unsigned*)&h0; pk.y = *(unsigned*)&h1;
        *(uint2*)&As[r * LDA + c4 * 4] = pk;
    }
    for (int i = t; i < 64 * 16; i += 256) {
        int k = i >> 4, c4 = i & 15;
        float4 v = *(const float4*)&Wm[k * 64 + c4 * 4];
        __half2 h0 = __floats2half2_rn(v.x, v.y);
        __half2 h1 = __floats2half2_rn(v.z, v.w);
        uint2 pk; pk.x = *(unsigned*)&h0; pk.y = *(unsigned*)&h1;
        *(uint2*)&Bs[k * 64 + c4 * 4] = pk;
    }
    __syncthreads();

    wmma::fragment<wmma::accumulator, 16, 16, 16, float> acc[4];
    #pragma unroll
    for (int nt = 0; nt < 4; nt++) wmma::fill_fragment(acc[nt], 0.f);
    #pragma unroll
    for (int ks = 0; ks < 4; ks++) {
        wmma::fragment<wmma::matrix_a, 16, 16, 16, __half, wmma::row_major> af;
        wmma::load_matrix_sync(af, As + (w * 16) * LDA + ks * 16, LDA);
        #pragma unroll
        for (int nt = 0; nt < 4; nt++) {
            wmma::fragment<wmma::matrix_b, 16, 16, 16, __half, wmma::row_major> bf;
            wmma::load_matrix_sync(bf, Bs + (ks * 16) * 64 + nt * 16, 64);
            wmma::mma_sync(acc[nt], af, bf, acc[nt]);
        }
    }
    __syncthreads();
    #pragma unroll
    for (int nt = 0; nt < 4; nt++)
        wmma::store_matrix_sync(Cs + (w * 16) * 64 + nt * 16, acc[nt], 64,
                                wmma::mem_row_major);
    __syncthreads();

    float ad0 = att[lane],      ad1 = att[lane + 32];
    float as0 = att[64 + lane], as1 = att[96 + lane];
    for (int rr = 0; rr < 16; rr++) {
        int r = w * 16 + rr;
        int node = n0 + r;
        float v0 = Cs[r * 64 + lane];
        float v1 = Cs[r * 64 + 32 + lane];
        float pd = v0 * ad0 + v1 * ad1;
        float ps = v0 * as0 + v1 * as1;
        #pragma unroll
        for (int o = 16; o; o >>= 1) {
            pd += __shfl_xor_sync(0xffffffffu, pd, o);
            ps += __shfl_xor_sync(0xffffffffu, ps, o);
        }
        float u0 = Cs[r * 64 + 2 * lane];
        float u1 = Cs[r * 64 + 2 * lane + 1];
        if (node < N) {
            g_hmh[node * (H / 2) + lane] = __floats2half2_rn(u0, u1);
            if (lane == 0) { g_pd[node] = pd; g_ps[node] = ps; }
        }
    }
}

// ---------------------------------------------------------------
// Counting sort of edges by dst
// ---------------------------------------------------------------
__global__ __launch_bounds__(256) void k_hist(const int* __restrict__ dst, int E)
{
    int i = blockIdx.x * blockDim.x + threadIdx.x;
    if (i < E) atomicAdd(&g_deg[dst[i]], 1);
}

__global__ __launch_bounds__(1024) void k_scan1(int N)
{
    __shared__ int ws[32];
    int t = threadIdx.x, lane = t & 31, w = t >> 5;
    int i = blockIdx.x * 1024 + t;
    int v = (i < N) ? g_deg[i] : 0;
    #pragma unroll
    for (int o = 1; o < 32; o <<= 1) {
        int u = __shfl_up_sync(0xffffffffu, v, o);
        if (lane >= o) v += u;
    }
    if (lane == 31) ws[w] = v;
    __syncthreads();
    if (w == 0) {
        int bsum = ws[lane];
        #pragma unroll
        for (int o = 1; o < 32; o <<= 1) {
            int u = __shfl_up_sync(0xffffffffu, bsum, o);
            if (lane >= o) bsum += u;
        }
        ws[lane] = bsum;
    }
    __syncthreads();
    if (w) v += ws[w - 1];
    if (i < N) g_off[i + 1] = v;
    if (t == 1023) g_bsum[blockIdx.x] = v;
}

// merged scan2+scan3: every block redundantly scans the block sums
__global__ __launch_bounds__(1024) void k_scan23(int N, int nb)
{
    __shared__ int s[128];
    int t = threadIdx.x;
    if (t < 128) s[t] = (t < nb) ? g_bsum[t] : 0;
    __syncthreads();
    #pragma unroll
    for (int o = 1; o < 128; o <<= 1) {
        int v = (t >= o && t < 128) ? s[t - o] : 0;
        __syncthreads();
        if (t < 128) s[t] += v;
        __syncthreads();
    }
    int add = blockIdx.x ? s[blockIdx.x - 1] : 0;
    int i = blockIdx.x * 1024 + t;
    if (i < N) g_off[i + 1] += add;
    if (i == 0) g_off[0] = 0;
}

__global__ __launch_bounds__(256) void k_sortscatter(
    const int* __restrict__ src, const int* __restrict__ dst,
    const int* __restrict__ typ, const float* __restrict__ conf, int E)
{
    int i = blockIdx.x * blockDim.x + threadIdx.x;
    if (i >= E) return;
    int d = dst[i];
    int pos = g_off[d] + atomicAdd(&g_cur[d], 1);
    int t = min(max(typ[i], 0), NREL - 1);
    g_srcs[pos] = (unsigned)src[i] | ((unsigned)t << 20);
    g_dsts[pos] = d;
    g_cf[pos]   = 0.1f * __logf(fmaxf(conf[i], 1e-6f));
}

// ---------------------------------------------------------------
// K_w: edge-parallel coalesced logit + exp
// ---------------------------------------------------------------
__global__ __launch_bounds__(256) void k_w(int E)
{
    int i = blockIdx.x * blockDim.x + threadIdx.x;
    if (i >= E) return;
    unsigned p = g_srcs[i];
    int d = g_dsts[i];
    float e = g_pd[d] + g_ps[p & 0xFFFFF] + g_q[p >> 20];
    e = e > 0.f ? e : 0.2f * e;
    e += g_cf[i];
    g_ex[i] = __expf(e);
}

// ---------------------------------------------------------------
// K_aggr: warp-per-node gather-sum (fp16 payload), software-pipelined
// metadata prefetch, fused softmax-normalize + residual + relu + LN.
// ---------------------------------------------------------------
__global__ __launch_bounds__(256) void k_aggr(
    const float* __restrict__ bias, const float* __restrict__ lng,
    const float* __restrict__ lnb, float* __restrict__ hout, int N)
{
    int n = (blockIdx.x * blockDim.x + threadIdx.x) >> 5;
    if (n >= N) return;
    int lane = threadIdx.x & 31;
    int half = lane >> 4;
    int l    = lane & 15;
    int beg = g_off[n], end = g_off[n + 1];
    float4 acc = make_float4(0.f, 0.f, 0.f, 0.f);
    float ssum = 0.f;

    int j = beg + half;
    unsigned p0 = 0, p1 = 0;
    float e0 = 0.f, e1 = 0.f;
    if (j < end)     { p0 = g_srcs[j];     e0 = g_ex[j]; }
    if (j + 2 < end) { p1 = g_srcs[j + 2]; e1 = g_ex[j + 2]; }
    for (; j + 2 < end; j += 4) {
        // prefetch next pair's metadata (padded arrays make OOB reads safe;
        // values only consumed if the next iteration's guard holds)
        unsigned q0 = g_srcs[j + 4], q1 = g_srcs[j + 6];
        float f0 = g_ex[j + 4], f1 = g_ex[j + 6];
        uint2 r0 = *(const uint2*)&g_hmh[(p0 & 0xFFFFF) * (H/2) + l * 2];
        uint2 r1 = *(const uint2*)&g_hmh[(p1 & 0xFFFFF) * (H/2) + l * 2];
        float2 a0 = __half22float2(*(__half2*)&r0.x);
        float2 b0 = __half22float2(*(__half2*)&r0.y);
        float2 a1 = __half22float2(*(__half2*)&r1.x);
        float2 b1 = __half22float2(*(__half2*)&r1.y);
        acc.x += e0 * a0.x + e1 * a1.x;
        acc.y += e0 * a0.y + e1 * a1.y;
        acc.z += e0 * b0.x + e1 * b1.x;
        acc.w += e0 * b0.y + e1 * b1.y;
        ssum += e0 + e1;
        p0 = q0; p1 = q1; e0 = f0; e1 = f1;
    }
    if (j < end) {
        uint2 r = *(const uint2*)&g_hmh[(p0 & 0xFFFFF) * (H/2) + l * 2];
        float2 a = __half22float2(*(__half2*)&r.x);
        float2 b = __half22float2(*(__half2*)&r.y);
        acc.x += e0 * a.x; acc.y += e0 * a.y;
        acc.z += e0 * b.x; acc.w += e0 * b.y;
        ssum += e0;
    }

    acc.x += __shfl_xor_sync(0xffffffffu, acc.x, 16);
    acc.y += __shfl_xor_sync(0xffffffffu, acc.y, 16);
    acc.z += __shfl_xor_sync(0xffffffffu, acc.z, 16);
    acc.w += __shfl_xor_sync(0xffffffffu, acc.w, 16);
    ssum  += __shfl_xor_sync(0xffffffffu, ssum,  16);
    float inv = (ssum > 0.f) ? (1.f / ssum) : 0.f;
    float4 hv = *(const float4*)&g_h[n * H + l * 4];
    float4 bb = *(const float4*)&bias[l * 4];
    float4 u;
    u.x = hv.x + fmaxf(acc.x * inv + bb.x, 0.f);
    u.y = hv.y + fmaxf(acc.y * inv + bb.y, 0.f);
    u.z = hv.z + fmaxf(acc.z * inv + bb.z, 0.f);
    u.w = hv.w + fmaxf(acc.w * inv + bb.w, 0.f);
    float s = u.x + u.y + u.z + u.w;
    #pragma unroll
    for (int o = 16; o; o >>= 1) s += __shfl_xor_sync(0xffffffffu, s, o);
    float mu = s * (1.f / 128.f);
    float4 d4 = make_float4(u.x - mu, u.y - mu, u.z - mu, u.w - mu);
    float vs = d4.x*d4.x + d4.y*d4.y + d4.z*d4.z + d4.w*d4.w;
    #pragma unroll
    for (int o = 16; o; o >>= 1) vs += __shfl_xor_sync(0xffffffffu, vs, o);
    float invs = rsqrtf(vs * (1.f / 128.f) + 1e-5f);
    if (half == 0) {
        float4 g4 = *(const float4*)&lng[l * 4];
        float4 b2 = *(const float4*)&lnb[l * 4];
        float* outp = hout ? hout : g_h;
        float4 o4;
        o4.x = d4.x * invs * g4.x + b2.x;
        o4.y = d4.y * invs * g4.y + b2.y;
        o4.z = d4.z * invs * g4.z + b2.z;
        o4.w = d4.w * invs * g4.w + b2.w;
        *(float4*)&outp[n * H + l * 4] = o4;
    }
}

// ---------------------------------------------------------------
extern "C" void kernel_launch(void* const* d_in, const int* in_sizes, int n_in,
                              void* d_out, int out_size)
{
    const float* x         = (const float*)d_in[0];
    const float* W_in      = (const float*)d_in[1];
    const float* b_in      = (const float*)d_in[2];
    const float* W_msg     = (const float*)d_in[3];
    const float* rel_emb   = (const float*)d_in[4];
    const float* W_relproj = (const float*)d_in[5];
    const float* att_vec   = (const float*)d_in[6];
    const float* bias      = (const float*)d_in[7];
    const float* ln_g      = (const float*)d_in[8];
    const float* ln_b      = (const float*)d_in[9];
    const float* edge_attr = (const float*)d_in[10];
    const int*   edge_index= (const int*)d_in[11];
    const int*   edge_type = (const int*)d_in[12];
    float* out = (float*)d_out;

    int N = in_sizes[0] / INF;
    int E = in_sizes[12];
    int L = in_sizes[7] / H;
    const int* src = edge_index;
    const int* dst = edge_index + E;
    int nb = (N + 1023) / 1024;

    k_input_mma<<<(N + 127) / 128, 256>>>(x, W_in, b_in, N);   // + zeroes deg/cur

    k_hist<<<(E + 255) / 256, 256>>>(dst, E);
    k_scan1<<<nb, 1024>>>(N);
    k_scan23<<<nb, 1024>>>(N, nb);
    k_sortscatter<<<(E + 255) / 256, 256>>>(src, dst, edge_type, edge_attr, E);

    for (int l = 0; l < L; l++) {
        k_msg_mma<<<(N + 127) / 128, 256>>>(W_msg + l * H * H,
                                            att_vec + l * 3 * H,
                                            rel_emb + l * NREL * 16,
                                            W_relproj + l * 16 * H, N);
        k_w<<<(E + 255) / 256, 256>>>(E);
        k_aggr<<<(N * 32 + 255) / 256, 256>>>(bias + l * H,
                                              ln_g + l * H, ln_b + l * H,
                                              (l == L - 1) ? out : (float*)nullptr,
                                              N);
    }
}